// round 2
// baseline (speedup 1.0000x reference)
#include <cuda_runtime.h>
#include <math.h>

// ---------------------------------------------------------------------------
// STCNNT cell: LN -> {convK,convQ (s2), convV} -> attention(T=32) -> convO +res
//              -> LN -> convM1+GELU -> convM2 +res
// Shapes: B=4, T=32 (BT=128), C=Cout=32, H=W=64, mixer=128, n_head=8, hd=4
// ---------------------------------------------------------------------------

#define BT 128

// scratch (device globals; no runtime allocation allowed)
__device__ float g_xn [BT * 32 * 64 * 64];    // 64 MB (xn, reused as xn2)
__device__ float g_q  [BT * 32 * 32 * 32];    // 16 MB
__device__ float g_k  [BT * 32 * 32 * 32];    // 16 MB
__device__ float g_v  [BT * 32 * 64 * 64];    // 64 MB
__device__ float g_att[4 * 8 * 32 * 32];      // 128 KB
__device__ float g_y  [BT * 32 * 64 * 64];    // 64 MB
__device__ float g_x1 [BT * 32 * 64 * 64];    // 64 MB
__device__ float g_h  [BT * 128 * 64 * 64];   // 256 MB

__device__ __forceinline__ float gelu_f(float v) {
    float u = 0.7978845608028654f * (v + 0.044715f * v * v * v);
    return 0.5f * v * (1.0f + tanhf(u));
}

// ---------------------------------------------------------------------------
// LayerNorm over (C,H,W) = 131072 elements per (b,t) sample. grid=128, block=256
// ---------------------------------------------------------------------------
__global__ void ln_kernel(const float* __restrict__ x, const float* __restrict__ g,
                          const float* __restrict__ b, float* __restrict__ out) {
    int n = blockIdx.x;
    const float4* x4 = (const float4*)(x + (size_t)n * 131072);
    float s = 0.f, ss = 0.f;
    for (int i = threadIdx.x; i < 32768; i += 256) {
        float4 v = x4[i];
        s  += v.x + v.y + v.z + v.w;
        ss += v.x * v.x + v.y * v.y + v.z * v.z + v.w * v.w;
    }
    __shared__ float rs[8], rss[8];
    #pragma unroll
    for (int o = 16; o > 0; o >>= 1) {
        s  += __shfl_xor_sync(0xffffffffu, s, o);
        ss += __shfl_xor_sync(0xffffffffu, ss, o);
    }
    int w = threadIdx.x >> 5;
    if ((threadIdx.x & 31) == 0) { rs[w] = s; rss[w] = ss; }
    __syncthreads();
    if (threadIdx.x < 32) {
        s  = (threadIdx.x < 8) ? rs[threadIdx.x]  : 0.f;
        ss = (threadIdx.x < 8) ? rss[threadIdx.x] : 0.f;
        #pragma unroll
        for (int o = 4; o > 0; o >>= 1) {
            s  += __shfl_xor_sync(0xffffffffu, s, o);
            ss += __shfl_xor_sync(0xffffffffu, ss, o);
        }
        if (threadIdx.x == 0) { rs[0] = s; rss[0] = ss; }
    }
    __syncthreads();
    float mean = rs[0] * (1.f / 131072.f);
    float var  = rss[0] * (1.f / 131072.f) - mean * mean;
    float rstd = rsqrtf(var + 1e-5f);
    const float4* g4 = (const float4*)g;
    const float4* b4 = (const float4*)b;
    float4* o4 = (float4*)(out + (size_t)n * 131072);
    for (int i = threadIdx.x; i < 32768; i += 256) {
        float4 v = x4[i], gg = g4[i], bb = b4[i], r;
        r.x = (v.x - mean) * rstd * gg.x + bb.x;
        r.y = (v.y - mean) * rstd * gg.y + bb.y;
        r.z = (v.z - mean) * rstd * gg.z + bb.z;
        r.w = (v.w - mean) * rstd * gg.w + bb.w;
        o4[i] = r;
    }
}

// ---------------------------------------------------------------------------
// 3x3 conv, stride 1, pad 1, 64x64 spatial. Block: 256 thr, out tile 64x16,
// 8 couts/block, 4 adjacent x-pixels/thread. Cin looped in chunks of 8.
// grid = (N, Cout/8, 4)
// ---------------------------------------------------------------------------
template<bool HASBIAS, bool GELU, bool RES>
__global__ void conv3x3_s1(const float* __restrict__ in, const float* __restrict__ wt,
                           const float* __restrict__ bias, const float* __restrict__ res,
                           float* __restrict__ out, int Cin, int Cout) {
    __shared__ float s_in[8][18][66];
    __shared__ float s_w[8][8][9];
    int n = blockIdx.x, co0 = blockIdx.y * 8, y0 = blockIdx.z * 16;
    int tid = threadIdx.x;
    int xg = tid & 15, row = tid >> 4;

    float acc[8][4];
    #pragma unroll
    for (int c = 0; c < 8; c++)
        #pragma unroll
        for (int p = 0; p < 4; p++) acc[c][p] = 0.f;

    for (int ci0 = 0; ci0 < Cin; ci0 += 8) {
        __syncthreads();
        for (int i = tid; i < 8 * 18 * 66; i += 256) {
            int ci = i / (18 * 66); int rem = i - ci * (18 * 66);
            int r = rem / 66, c = rem - r * 66;
            int gy = y0 + r - 1, gx = c - 1;
            float v = 0.f;
            if (gy >= 0 && gy < 64 && gx >= 0 && gx < 64)
                v = in[(((size_t)n * Cin + (ci0 + ci)) * 64 + gy) * 64 + gx];
            s_in[ci][r][c] = v;
        }
        for (int i = tid; i < 8 * 8 * 9; i += 256) {
            int co = i / 72; int rem = i - co * 72; int ci = rem / 9; int t = rem - ci * 9;
            s_w[co][ci][t] = wt[((size_t)(co0 + co) * Cin + (ci0 + ci)) * 9 + t];
        }
        __syncthreads();

        for (int ci = 0; ci < 8; ci++) {
            float xv[3][6];
            #pragma unroll
            for (int dy = 0; dy < 3; dy++)
                #pragma unroll
                for (int j = 0; j < 6; j++)
                    xv[dy][j] = s_in[ci][row + dy][4 * xg + j];
            #pragma unroll
            for (int dy = 0; dy < 3; dy++) {
                #pragma unroll
                for (int dx = 0; dx < 3; dx++) {
                    float wv[8];
                    #pragma unroll
                    for (int c = 0; c < 8; c++) wv[c] = s_w[c][ci][dy * 3 + dx];
                    #pragma unroll
                    for (int p = 0; p < 4; p++) {
                        float xx = xv[dy][p + dx];
                        #pragma unroll
                        for (int c = 0; c < 8; c++) acc[c][p] += xx * wv[c];
                    }
                }
            }
        }
    }

    int y = y0 + row;
    #pragma unroll
    for (int c = 0; c < 8; c++) {
        float bv = HASBIAS ? bias[co0 + c] : 0.f;
        float vals[4];
        #pragma unroll
        for (int p = 0; p < 4; p++) {
            float v = acc[c][p] + bv;
            if (GELU) v = gelu_f(v);
            vals[p] = v;
        }
        size_t oidx = (((size_t)n * Cout + co0 + c) * 64 + y) * 64 + 4 * xg;
        if (RES) {
            float4 rv = *(const float4*)(res + oidx);
            vals[0] += rv.x; vals[1] += rv.y; vals[2] += rv.z; vals[3] += rv.w;
        }
        float4 o; o.x = vals[0]; o.y = vals[1]; o.z = vals[2]; o.w = vals[3];
        *(float4*)(out + oidx) = o;
    }
}

// ---------------------------------------------------------------------------
// 3x3 conv, stride 2, pad 1: 64x64 -> 32x32, Cin=Cout=32, no bias.
// Block: 64 thr, out tile 32x8, 8 couts/block, 4 x-pixels/thread.
// grid = (N, 4, 4)
// ---------------------------------------------------------------------------
__global__ void conv3x3_s2(const float* __restrict__ in, const float* __restrict__ wt,
                           float* __restrict__ out) {
    __shared__ float s_in[8][17][66];
    __shared__ float s_w[8][8][9];
    int n = blockIdx.x, co0 = blockIdx.y * 8, y0 = blockIdx.z * 8;
    int tid = threadIdx.x;            // 64 threads
    int xg = tid & 7, row = tid >> 3; // 8 x-groups, 8 rows

    float acc[8][4];
    #pragma unroll
    for (int c = 0; c < 8; c++)
        #pragma unroll
        for (int p = 0; p < 4; p++) acc[c][p] = 0.f;

    for (int ci0 = 0; ci0 < 32; ci0 += 8) {
        __syncthreads();
        for (int i = tid; i < 8 * 17 * 66; i += 64) {
            int ci = i / (17 * 66); int rem = i - ci * (17 * 66);
            int r = rem / 66, c = rem - r * 66;
            int gy = 2 * y0 - 1 + r, gx = c - 1;
            float v = 0.f;
            if (gy >= 0 && gy < 64 && gx >= 0 && gx < 64)
                v = in[(((size_t)n * 32 + (ci0 + ci)) * 64 + gy) * 64 + gx];
            s_in[ci][r][c] = v;
        }
        for (int i = tid; i < 576; i += 64) {
            int co = i / 72; int rem = i - co * 72; int ci = rem / 9; int t = rem - ci * 9;
            s_w[co][ci][t] = wt[((size_t)(co0 + co) * 32 + (ci0 + ci)) * 9 + t];
        }
        __syncthreads();

        for (int ci = 0; ci < 8; ci++) {
            float xv[3][9];
            #pragma unroll
            for (int dy = 0; dy < 3; dy++)
                #pragma unroll
                for (int j = 0; j < 9; j++)
                    xv[dy][j] = s_in[ci][2 * row + dy][8 * xg + j];
            #pragma unroll
            for (int dy = 0; dy < 3; dy++) {
                #pragma unroll
                for (int dx = 0; dx < 3; dx++) {
                    float wv[8];
                    #pragma unroll
                    for (int c = 0; c < 8; c++) wv[c] = s_w[c][ci][dy * 3 + dx];
                    #pragma unroll
                    for (int p = 0; p < 4; p++) {
                        float xx = xv[dy][2 * p + dx];
                        #pragma unroll
                        for (int c = 0; c < 8; c++) acc[c][p] += xx * wv[c];
                    }
                }
            }
        }
    }

    int y = y0 + row;
    #pragma unroll
    for (int c = 0; c < 8; c++) {
        size_t oidx = (((size_t)n * 32 + co0 + c) * 32 + y) * 32 + 4 * xg;
        float4 o; o.x = acc[c][0]; o.y = acc[c][1]; o.z = acc[c][2]; o.w = acc[c][3];
        *(float4*)(out + oidx) = o;
    }
}

// ---------------------------------------------------------------------------
// att[b,h,t,s] = softmax_s( q[b,h,t,:] . k[b,h,s,:] / 64 ), d_k = 4096
// q,k layout: [BT, 32, 32, 32]; (b,t,h) slice contiguous 4096 floats.
// grid = 1024 (b*8*32 + ...), block = 256 (8 warps; warp computes 4 s-dots)
// ---------------------------------------------------------------------------
__global__ void qk_softmax_kernel(const float* __restrict__ q, const float* __restrict__ k,
                                  float* __restrict__ att) {
    int bx = blockIdx.x;
    int t = bx & 31, bh = bx >> 5, h = bh & 7, b = bh >> 3;
    int lane = threadIdx.x & 31, w = threadIdx.x >> 5;
    const float4* q4 = (const float4*)(q + ((size_t)(b * 32 + t) * 32 + h * 4) * 1024);
    __shared__ float sS[32];
    #pragma unroll
    for (int si = 0; si < 4; si++) {
        int s = w * 4 + si;
        const float4* k4 = (const float4*)(k + ((size_t)(b * 32 + s) * 32 + h * 4) * 1024);
        float acc = 0.f;
        for (int d = lane; d < 1024; d += 32) {
            float4 qv = q4[d], kv = k4[d];
            acc += qv.x * kv.x + qv.y * kv.y + qv.z * kv.z + qv.w * kv.w;
        }
        #pragma unroll
        for (int o = 16; o > 0; o >>= 1) acc += __shfl_xor_sync(0xffffffffu, acc, o);
        if (lane == 0) sS[s] = acc * (1.f / 64.f);
    }
    __syncthreads();
    if (threadIdx.x < 32) {
        float v = sS[threadIdx.x];
        float m = v;
        #pragma unroll
        for (int o = 16; o > 0; o >>= 1) m = fmaxf(m, __shfl_xor_sync(0xffffffffu, m, o));
        float e = expf(v - m);
        float sum = e;
        #pragma unroll
        for (int o = 16; o > 0; o >>= 1) sum += __shfl_xor_sync(0xffffffffu, sum, o);
        att[(size_t)bx * 32 + threadIdx.x] = e / sum;
    }
}

// ---------------------------------------------------------------------------
// y[b,h,t,d] = sum_s att[b,h,t,s] * v[b,h,s,d], d_v = 16384.
// grid = (32, 64), block = 256; thread owns one d, 32 t-accumulators.
// ---------------------------------------------------------------------------
__global__ void av_kernel(const float* __restrict__ att, const float* __restrict__ v,
                          float* __restrict__ y) {
    int bh = blockIdx.x, b = bh >> 3, h = bh & 7;
    int d = blockIdx.y * 256 + threadIdx.x;
    __shared__ __align__(16) float sA[32][36];  // sA[s][t] (transposed)
    for (int i = threadIdx.x; i < 1024; i += 256) {
        int t = i >> 5, s = i & 31;
        sA[s][t] = att[((size_t)bh * 32 + t) * 32 + s];
    }
    __syncthreads();
    const float* vb = v + (size_t)b * 32 * 131072 + (size_t)h * 16384 + d;
    float acc[32];
    #pragma unroll
    for (int t = 0; t < 32; t++) acc[t] = 0.f;
    #pragma unroll 4
    for (int s = 0; s < 32; s++) {
        float vv = vb[(size_t)s * 131072];
        const float4* a4 = (const float4*)&sA[s][0];
        #pragma unroll
        for (int t4 = 0; t4 < 8; t4++) {
            float4 a = a4[t4];
            acc[4 * t4 + 0] += a.x * vv;
            acc[4 * t4 + 1] += a.y * vv;
            acc[4 * t4 + 2] += a.z * vv;
            acc[4 * t4 + 3] += a.w * vv;
        }
    }
    float* yb = y + (size_t)b * 32 * 131072 + (size_t)h * 16384 + d;
    #pragma unroll
    for (int t = 0; t < 32; t++) yb[(size_t)t * 131072] = acc[t];
}

// ---------------------------------------------------------------------------
extern "C" void kernel_launch(void* const* d_in, const int* in_sizes, int n_in,
                              void* d_out, int out_size) {
    const float* x   = (const float*)d_in[0];
    const float* n1g = (const float*)d_in[1];
    const float* n1b = (const float*)d_in[2];
    const float* n2g = (const float*)d_in[3];
    const float* n2b = (const float*)d_in[4];
    const float* Wk  = (const float*)d_in[5];
    const float* Wq  = (const float*)d_in[6];
    const float* Wv  = (const float*)d_in[7];
    const float* Wo  = (const float*)d_in[8];
    const float* bo  = (const float*)d_in[9];
    const float* Wm1 = (const float*)d_in[10];
    const float* bm1 = (const float*)d_in[11];
    const float* Wm2 = (const float*)d_in[12];
    const float* bm2 = (const float*)d_in[13];
    float* out = (float*)d_out;

    float *xn, *q, *k, *v, *att, *y, *x1, *h;
    cudaGetSymbolAddress((void**)&xn,  g_xn);
    cudaGetSymbolAddress((void**)&q,   g_q);
    cudaGetSymbolAddress((void**)&k,   g_k);
    cudaGetSymbolAddress((void**)&v,   g_v);
    cudaGetSymbolAddress((void**)&att, g_att);
    cudaGetSymbolAddress((void**)&y,   g_y);
    cudaGetSymbolAddress((void**)&x1,  g_x1);
    cudaGetSymbolAddress((void**)&h,   g_h);

    // 1. LN1
    ln_kernel<<<128, 256>>>(x, n1g, n1b, xn);
    // 2-4. k, q (stride-2), v (stride-1) convs
    conv3x3_s2<<<dim3(128, 4, 4), 64>>>(xn, Wk, k);
    conv3x3_s2<<<dim3(128, 4, 4), 64>>>(xn, Wq, q);
    conv3x3_s1<false, false, false><<<dim3(128, 4, 4), 256>>>(xn, Wv, nullptr, nullptr, v, 32, 32);
    // 5. scores + softmax
    qk_softmax_kernel<<<1024, 256>>>(q, k, att);
    // 6. att @ v
    av_kernel<<<dim3(32, 64), 256>>>(att, v, y);
    // 7. output projection conv + bias + residual(x)
    conv3x3_s1<true, false, true><<<dim3(128, 4, 4), 256>>>(y, Wo, bo, x, x1, 32, 32);
    // 8. LN2
    ln_kernel<<<128, 256>>>(x1, n2g, n2b, xn);
    // 9. mixer conv1 + bias + GELU (32 -> 128)
    conv3x3_s1<true, true, false><<<dim3(128, 16, 4), 256>>>(xn, Wm1, bm1, nullptr, h, 32, 128);
    // 10. mixer conv2 + bias + residual(x1) (128 -> 32) -> final output
    conv3x3_s1<true, false, true><<<dim3(128, 4, 4), 256>>>(h, Wm2, bm2, x1, out, 128, 32);
}

// round 4
// speedup vs baseline: 1.6833x; 1.6833x over previous
#include <cuda_runtime.h>
#include <cuda_bf16.h>
#include <math.h>
#include <cstdint>

// ===========================================================================
// STCNNT cell, convs as implicit GEMM on mma.sync (HMMA bf16, fp32 accum,
// hi/lo 3-product split). M=couts(32/CTA-slice), N=128 pixels, K=9*Cin.
// B=4, T=32 (BT=128), C=32, H=W=64, mixer=128, n_head=8
// ===========================================================================

#define BT 128

// ---------------- device scratch ----------------
__device__ float g_xpad[BT * 32 * 66 * 66];
__device__ float g_ypad[BT * 32 * 66 * 66];
__device__ float g_hpad[BT * 128 * 66 * 66];
__device__ float g_v  [BT * 32 * 64 * 64];
__device__ float g_q  [BT * 32 * 32 * 32];
__device__ float g_k  [BT * 32 * 32 * 32];
__device__ float g_att[4 * 8 * 32 * 32];
__device__ float g_x1 [BT * 32 * 64 * 64];
#define WSTRIDE 46080   // halfs per (conv, hi|lo): max KB*9*COUT*40
__device__ __align__(16) __nv_bfloat16 g_wb[6 * 2 * WSTRIDE];

__device__ __forceinline__ float gelu_f(float v) {
    float u = 0.7978845608028654f * (v + 0.044715f * v * v * v);
    return 0.5f * v * (1.0f + tanhf(u));
}

__device__ __forceinline__ void mma_bf16(float* c, uint32_t a0, uint32_t a1,
                                         uint32_t a2, uint32_t a3,
                                         uint32_t b0, uint32_t b1) {
    asm volatile(
        "mma.sync.aligned.m16n8k16.row.col.f32.bf16.bf16.f32 "
        "{%0,%1,%2,%3}, {%4,%5,%6,%7}, {%8,%9}, {%0,%1,%2,%3};"
        : "+f"(c[0]), "+f"(c[1]), "+f"(c[2]), "+f"(c[3])
        : "r"(a0), "r"(a1), "r"(a2), "r"(a3), "r"(b0), "r"(b1));
}

// ---------------------------------------------------------------------------
// zero 1-cell border of padded [128][CH][66][66]
// ---------------------------------------------------------------------------
__global__ void zb_kernel(float* __restrict__ p, int CH) {
    int idx = blockIdx.x * blockDim.x + threadIdx.x;
    int total = 128 * CH * 260;
    if (idx >= total) return;
    int sc = idx / 260, j = idx - sc * 260;
    int yy, xx;
    if (j < 66)       { yy = 0;       xx = j; }
    else if (j < 132) { yy = 65;      xx = j - 66; }
    else if (j < 196) { yy = j - 131; xx = 0; }
    else              { yy = j - 195; xx = 65; }
    p[(size_t)sc * 4356 + yy * 66 + xx] = 0.f;
}

// ---------------------------------------------------------------------------
// weight prep: fp32 [Cout][Cin][3][3] -> bf16 hi/lo, layout
// [ciblk][tap][cout][40] (k-slot 0..31 real, 32..39 zero pad)
// ---------------------------------------------------------------------------
__global__ void wprep_kernel(const float* __restrict__ w,
                             __nv_bfloat16* __restrict__ hi,
                             __nv_bfloat16* __restrict__ lo,
                             int CIN, int COUT) {
    int KB = CIN / 32;
    int total = KB * 9 * COUT * 40;
    int idx = blockIdx.x * blockDim.x + threadIdx.x;
    if (idx >= total) return;
    int kk = idx % 40;
    int t1 = idx / 40;
    int cout = t1 % COUT;
    int t2 = t1 / COUT;
    int tap = t2 % 9, cib = t2 / 9;
    float wv = (kk < 32) ? w[((size_t)cout * CIN + cib * 32 + kk) * 9 + tap] : 0.f;
    __nv_bfloat16 h = __float2bfloat16_rn(wv);
    __nv_bfloat16 l = __float2bfloat16_rn(wv - __bfloat162float(h));
    hi[idx] = h;
    lo[idx] = l;
}

// ---------------------------------------------------------------------------
// LayerNorm over (C,H,W)=131072 -> padded [n][32][66][66]. grid=128, block=256
// ---------------------------------------------------------------------------
__global__ void ln_pad_kernel(const float* __restrict__ x, const float* __restrict__ g,
                              const float* __restrict__ b, float* __restrict__ out) {
    int n = blockIdx.x;
    const float4* x4 = (const float4*)(x + (size_t)n * 131072);
    float s = 0.f, ss = 0.f;
    for (int i = threadIdx.x; i < 32768; i += 256) {
        float4 v = x4[i];
        s  += v.x + v.y + v.z + v.w;
        ss += v.x * v.x + v.y * v.y + v.z * v.z + v.w * v.w;
    }
    __shared__ float rs[8], rss[8];
    #pragma unroll
    for (int o = 16; o > 0; o >>= 1) {
        s  += __shfl_xor_sync(0xffffffffu, s, o);
        ss += __shfl_xor_sync(0xffffffffu, ss, o);
    }
    int w = threadIdx.x >> 5;
    if ((threadIdx.x & 31) == 0) { rs[w] = s; rss[w] = ss; }
    __syncthreads();
    if (threadIdx.x < 32) {
        s  = (threadIdx.x < 8) ? rs[threadIdx.x]  : 0.f;
        ss = (threadIdx.x < 8) ? rss[threadIdx.x] : 0.f;
        #pragma unroll
        for (int o = 4; o > 0; o >>= 1) {
            s  += __shfl_xor_sync(0xffffffffu, s, o);
            ss += __shfl_xor_sync(0xffffffffu, ss, o);
        }
        if (threadIdx.x == 0) { rs[0] = s; rss[0] = ss; }
    }
    __syncthreads();
    float mean = rs[0] * (1.f / 131072.f);
    float var  = rss[0] * (1.f / 131072.f) - mean * mean;
    float rstd = rsqrtf(var + 1e-5f);
    const float4* g4 = (const float4*)g;
    const float4* b4 = (const float4*)b;
    float* ob = out + (size_t)n * 32 * 4356;
    for (int i = threadIdx.x; i < 32768; i += 256) {
        float4 v = x4[i], gg = g4[i], bb = b4[i];
        int e = i * 4;
        int ci = e >> 12, rem = e & 4095;
        int y = rem >> 6, xx = rem & 63;
        float* o = ob + (size_t)ci * 4356 + (y + 1) * 66 + (xx + 1);
        o[0] = (v.x - mean) * rstd * gg.x + bb.x;
        o[1] = (v.y - mean) * rstd * gg.y + bb.y;
        o[2] = (v.z - mean) * rstd * gg.z + bb.z;
        o[3] = (v.w - mean) * rstd * gg.w + bb.w;
    }
}

// ---------------------------------------------------------------------------
// HMMA implicit-GEMM 3x3 conv. Input padded [n][CIN][66][66].
// grid=(128, ytiles, COUT/32), block=128 (4 warps).
// CTA: 32 couts x 128 pixels. Warp: 32 couts x 32 pixels.
// smem: s_in [NR][66][40(ci pad)] hi/lo bf16, s_w [9][32][40] hi/lo bf16.
// ---------------------------------------------------------------------------
template<int CIN, int COUT, int STRIDE, bool HASBIAS, bool DOGELU, bool RES, bool PADOUT>
__global__ void __launch_bounds__(128) convT(
    const float* __restrict__ in,
    const __nv_bfloat16* __restrict__ wph,
    const __nv_bfloat16* __restrict__ wpl,
    const float* __restrict__ bias,
    const float* __restrict__ res,
    float* __restrict__ out) {

    constexpr int NR    = (STRIDE == 1) ? 4 : 9;
    constexpr int KB    = CIN / 32;
    constexpr int S_IN  = NR * 66 * 40;
    constexpr int S_W   = 9 * 32 * 40;
    constexpr int WOUT  = 64 / STRIDE;
    constexpr int RPT   = 128 / WOUT;           // rows per tile: 2 (s1) / 4 (s2)

    extern __shared__ __align__(16) __nv_bfloat16 smem[];
    __nv_bfloat16* s_ih = smem;
    __nv_bfloat16* s_il = smem + S_IN;
    __nv_bfloat16* s_wh = smem + 2 * S_IN;
    __nv_bfloat16* s_wl = s_wh + S_W;

    int n = blockIdx.x, by = blockIdx.y, cb = blockIdx.z;
    int tid = threadIdx.x, lane = tid & 31, wid = tid >> 5;
    int g = lane >> 2, tg = lane & 3;
    int row0 = by * RPT * STRIDE;               // padded base row

    // per-lane B-fragment base smem offsets (pixel -> [row*S][x*S])
    int off0[4];
    #pragma unroll
    for (int nt = 0; nt < 4; nt++) {
        int p = wid * 32 + nt * 8 + g;
        int r = p / WOUT, xx = p % WOUT;
        off0[nt] = (r * STRIDE * 66 + xx * STRIDE) * 40;
    }

    float acc[2][4][4] = {};

    for (int cib = 0; cib < KB; cib++) {
        if (cib) __syncthreads();
        // build s_in (hi/lo bf16), layout [rr*66+cc][ci]
        const float* inb = in + ((size_t)n * CIN + cib * 32) * 4356 + row0 * 66;
        for (int j = tid; j < NR * 66 * 32; j += 128) {
            int ci = j / (NR * 66);
            int rem = j - ci * (NR * 66);
            float v = inb[(size_t)ci * 4356 + rem];
            __nv_bfloat16 h = __float2bfloat16_rn(v);
            __nv_bfloat16 l = __float2bfloat16_rn(v - __bfloat162float(h));
            int so = rem * 40 + ci;
            s_ih[so] = h;
            s_il[so] = l;
        }
        // copy pre-swizzled weights (flat float4)
        {
            const float4* srch = (const float4*)wph;
            const float4* srcl = (const float4*)wpl;
            float4* dsth = (float4*)s_wh;
            float4* dstl = (float4*)s_wl;
            for (int i = tid; i < 1440; i += 128) {     // 9*32*40 halfs / 8
                int tap = i / 160, rem = i - tap * 160;
                int si = ((cib * 9 + tap) * COUT + cb * 32) * 5 + rem;
                dsth[i] = srch[si];
                dstl[i] = srcl[si];
            }
        }
        __syncthreads();

        #pragma unroll 3
        for (int tap = 0; tap < 9; tap++) {
            int dy = tap / 3, dx = tap - dy * 3;
            int toff = (dy * 66 + dx) * 40;
            const __nv_bfloat16* wh = s_wh + tap * 1280;
            const __nv_bfloat16* wl = s_wl + tap * 1280;
            #pragma unroll
            for (int kc = 0; kc < 2; kc++) {
                uint32_t Ah[2][4], Al[2][4];
                #pragma unroll
                for (int mt = 0; mt < 2; mt++) {
                    int a0 = (mt * 16 + g) * 40 + kc * 16 + tg * 2;
                    Ah[mt][0] = *(const uint32_t*)(wh + a0);
                    Ah[mt][1] = *(const uint32_t*)(wh + a0 + 320);
                    Ah[mt][2] = *(const uint32_t*)(wh + a0 + 8);
                    Ah[mt][3] = *(const uint32_t*)(wh + a0 + 328);
                    Al[mt][0] = *(const uint32_t*)(wl + a0);
                    Al[mt][1] = *(const uint32_t*)(wl + a0 + 320);
                    Al[mt][2] = *(const uint32_t*)(wl + a0 + 8);
                    Al[mt][3] = *(const uint32_t*)(wl + a0 + 328);
                }
                #pragma unroll
                for (int nt = 0; nt < 4; nt++) {
                    int bo = off0[nt] + toff + kc * 16 + tg * 2;
                    uint32_t bh0 = *(const uint32_t*)(s_ih + bo);
                    uint32_t bh1 = *(const uint32_t*)(s_ih + bo + 8);
                    uint32_t bl0 = *(const uint32_t*)(s_il + bo);
                    uint32_t bl1 = *(const uint32_t*)(s_il + bo + 8);
                    mma_bf16(acc[0][nt], Ah[0][0], Ah[0][1], Ah[0][2], Ah[0][3], bh0, bh1);
                    mma_bf16(acc[1][nt], Ah[1][0], Ah[1][1], Ah[1][2], Ah[1][3], bh0, bh1);
                    mma_bf16(acc[0][nt], Al[0][0], Al[0][1], Al[0][2], Al[0][3], bh0, bh1);
                    mma_bf16(acc[1][nt], Al[1][0], Al[1][1], Al[1][2], Al[1][3], bh0, bh1);
                    mma_bf16(acc[0][nt], Ah[0][0], Ah[0][1], Ah[0][2], Ah[0][3], bl0, bl1);
                    mma_bf16(acc[1][nt], Ah[1][0], Ah[1][1], Ah[1][2], Ah[1][3], bl0, bl1);
                }
            }
        }
    }

    // epilogue: C rows = couts, cols = pixels (c0,c1 x-adjacent)
    #pragma unroll
    for (int mt = 0; mt < 2; mt++) {
        int co = cb * 32 + mt * 16 + g;
        float bv0 = 0.f, bv1 = 0.f;
        if (HASBIAS) { bv0 = bias[co]; bv1 = bias[co + 8]; }
        #pragma unroll
        for (int nt = 0; nt < 4; nt++) {
            int p = wid * 32 + nt * 8 + 2 * tg;
            int r = p / WOUT, xx = p % WOUT;
            int oy = by * RPT + r;
            float v0 = acc[mt][nt][0] + bv0;
            float v1 = acc[mt][nt][1] + bv0;
            float v2 = acc[mt][nt][2] + bv1;
            float v3 = acc[mt][nt][3] + bv1;
            if (DOGELU) { v0 = gelu_f(v0); v1 = gelu_f(v1); v2 = gelu_f(v2); v3 = gelu_f(v3); }
            if (PADOUT) {
                float* o = out + ((size_t)n * COUT + co) * 4356 + (oy + 1) * 66 + (xx + 1);
                o[0] = v0; o[1] = v1;
                o[8 * 4356] = v2; o[8 * 4356 + 1] = v3;
            } else {
                size_t oi = ((size_t)n * COUT + co) * (WOUT * WOUT) + oy * WOUT + xx;
                size_t oi2 = oi + (size_t)8 * WOUT * WOUT;
                if (RES) {
                    float2 r0 = *(const float2*)(res + oi);
                    float2 r1 = *(const float2*)(res + oi2);
                    v0 += r0.x; v1 += r0.y; v2 += r1.x; v3 += r1.y;
                }
                float2 w0; w0.x = v0; w0.y = v1;
                float2 w1; w1.x = v2; w1.y = v3;
                *(float2*)(out + oi)  = w0;
                *(float2*)(out + oi2) = w1;
            }
        }
    }
}

// ---------------------------------------------------------------------------
// att = softmax(q.k/64); q,k: [BT,32,32,32]. grid=1024, block=256
// ---------------------------------------------------------------------------
__global__ void qk_softmax_kernel(const float* __restrict__ q, const float* __restrict__ k,
                                  float* __restrict__ att) {
    int bx = blockIdx.x;
    int t = bx & 31, bh = bx >> 5, h = bh & 7, b = bh >> 3;
    int lane = threadIdx.x & 31, w = threadIdx.x >> 5;
    const float4* q4 = (const float4*)(q + ((size_t)(b * 32 + t) * 32 + h * 4) * 1024);
    __shared__ float sS[32];
    #pragma unroll
    for (int si = 0; si < 4; si++) {
        int s = w * 4 + si;
        const float4* k4 = (const float4*)(k + ((size_t)(b * 32 + s) * 32 + h * 4) * 1024);
        float acc = 0.f;
        for (int d = lane; d < 1024; d += 32) {
            float4 qv = q4[d], kv = k4[d];
            acc += qv.x * kv.x + qv.y * kv.y + qv.z * kv.z + qv.w * kv.w;
        }
        #pragma unroll
        for (int o = 16; o > 0; o >>= 1) acc += __shfl_xor_sync(0xffffffffu, acc, o);
        if (lane == 0) sS[s] = acc * (1.f / 64.f);
    }
    __syncthreads();
    if (threadIdx.x < 32) {
        float v = sS[threadIdx.x];
        float m = v;
        #pragma unroll
        for (int o = 16; o > 0; o >>= 1) m = fmaxf(m, __shfl_xor_sync(0xffffffffu, m, o));
        float e = expf(v - m);
        float sum = e;
        #pragma unroll
        for (int o = 16; o > 0; o >>= 1) sum += __shfl_xor_sync(0xffffffffu, sum, o);
        att[(size_t)bx * 32 + threadIdx.x] = e / sum;
    }
}

// ---------------------------------------------------------------------------
// y = att @ v -> PADDED ypad. grid=(32,64), block=256
// ---------------------------------------------------------------------------
__global__ void av_kernel(const float* __restrict__ att, const float* __restrict__ v,
                          float* __restrict__ ypad) {
    int bh = blockIdx.x, b = bh >> 3, h = bh & 7;
    int d = blockIdx.y * 256 + threadIdx.x;
    int cil = d >> 12, yy = (d >> 6) & 63, xx = d & 63;
    __shared__ __align__(16) float sA[32][36];
    for (int i = threadIdx.x; i < 1024; i += 256) {
        int t = i >> 5, s = i & 31;
        sA[s][t] = att[((size_t)bh * 32 + t) * 32 + s];
    }
    __syncthreads();
    const float* vb = v + (size_t)b * 32 * 131072 + (size_t)h * 16384 + d;
    float acc[32];
    #pragma unroll
    for (int t = 0; t < 32; t++) acc[t] = 0.f;
    #pragma unroll 4
    for (int s = 0; s < 32; s++) {
        float vv = vb[(size_t)s * 131072];
        const float4* a4 = (const float4*)&sA[s][0];
        #pragma unroll
        for (int t4 = 0; t4 < 8; t4++) {
            float4 a = a4[t4];
            acc[4 * t4 + 0] += a.x * vv;
            acc[4 * t4 + 1] += a.y * vv;
            acc[4 * t4 + 2] += a.z * vv;
            acc[4 * t4 + 3] += a.w * vv;
        }
    }
    int ci = h * 4 + cil;
    size_t base = (((size_t)(b * 32) * 32 + ci) * 66 + (yy + 1)) * 66 + (xx + 1);
    #pragma unroll
    for (int t = 0; t < 32; t++) ypad[base + (size_t)t * 32 * 4356] = acc[t];
}

// ---------------------------------------------------------------------------
extern "C" void kernel_launch(void* const* d_in, const int* in_sizes, int n_in,
                              void* d_out, int out_size) {
    const float* x   = (const float*)d_in[0];
    const float* n1g = (const float*)d_in[1];
    const float* n1b = (const float*)d_in[2];
    const float* n2g = (const float*)d_in[3];
    const float* n2b = (const float*)d_in[4];
    const float* Wk  = (const float*)d_in[5];
    const float* Wq  = (const float*)d_in[6];
    const float* Wv  = (const float*)d_in[7];
    const float* Wo  = (const float*)d_in[8];
    const float* bo  = (const float*)d_in[9];
    const float* Wm1 = (const float*)d_in[10];
    const float* bm1 = (const float*)d_in[11];
    const float* Wm2 = (const float*)d_in[12];
    const float* bm2 = (const float*)d_in[13];
    float* out = (float*)d_out;

    float *xpad, *ypad, *hpad, *v, *q, *k, *att, *x1;
    __nv_bfloat16* wb;
    cudaGetSymbolAddress((void**)&xpad, g_xpad);
    cudaGetSymbolAddress((void**)&ypad, g_ypad);
    cudaGetSymbolAddress((void**)&hpad, g_hpad);
    cudaGetSymbolAddress((void**)&v,    g_v);
    cudaGetSymbolAddress((void**)&q,    g_q);
    cudaGetSymbolAddress((void**)&k,    g_k);
    cudaGetSymbolAddress((void**)&att,  g_att);
    cudaGetSymbolAddress((void**)&x1,   g_x1);
    cudaGetSymbolAddress((void**)&wb,   g_wb);

    __nv_bfloat16 *wkh = wb + 0 * 2 * WSTRIDE, *wkl = wkh + WSTRIDE;
    __nv_bfloat16 *wqh = wb + 1 * 2 * WSTRIDE, *wql = wqh + WSTRIDE;
    __nv_bfloat16 *wvh = wb + 2 * 2 * WSTRIDE, *wvl = wvh + WSTRIDE;
    __nv_bfloat16 *woh = wb + 3 * 2 * WSTRIDE, *wol = woh + WSTRIDE;
    __nv_bfloat16 *w1h = wb + 4 * 2 * WSTRIDE, *w1l = w1h + WSTRIDE;
    __nv_bfloat16 *w2h = wb + 5 * 2 * WSTRIDE, *w2l = w2h + WSTRIDE;

    // opt-in dynamic smem (s1: 88320 B, s2: 141120 B)
    const int SM1 = (2 * (4 * 66 * 40) + 2 * (9 * 32 * 40)) * 2;
    const int SM2 = (2 * (9 * 66 * 40) + 2 * (9 * 32 * 40)) * 2;
    cudaFuncSetAttribute(convT<32, 32, 2, false, false, false, false>,
                         cudaFuncAttributeMaxDynamicSharedMemorySize, SM2);
    cudaFuncSetAttribute(convT<32, 32, 1, false, false, false, false>,
                         cudaFuncAttributeMaxDynamicSharedMemorySize, SM1);
    cudaFuncSetAttribute(convT<32, 32, 1, true, false, true, false>,
                         cudaFuncAttributeMaxDynamicSharedMemorySize, SM1);
    cudaFuncSetAttribute(convT<32, 128, 1, true, true, false, true>,
                         cudaFuncAttributeMaxDynamicSharedMemorySize, SM1);
    cudaFuncSetAttribute(convT<128, 32, 1, true, false, true, false>,
                         cudaFuncAttributeMaxDynamicSharedMemorySize, SM1);

    // border zeroing + weight prep
    zb_kernel<<<(128 * 32 * 260 + 255) / 256, 256>>>(xpad, 32);
    zb_kernel<<<(128 * 32 * 260 + 255) / 256, 256>>>(ypad, 32);
    zb_kernel<<<(128 * 128 * 260 + 255) / 256, 256>>>(hpad, 128);
    wprep_kernel<<<(9 * 32 * 40 + 255) / 256, 256>>>(Wk,  wkh, wkl, 32, 32);
    wprep_kernel<<<(9 * 32 * 40 + 255) / 256, 256>>>(Wq,  wqh, wql, 32, 32);
    wprep_kernel<<<(9 * 32 * 40 + 255) / 256, 256>>>(Wv,  wvh, wvl, 32, 32);
    wprep_kernel<<<(9 * 32 * 40 + 255) / 256, 256>>>(Wo,  woh, wol, 32, 32);
    wprep_kernel<<<(9 * 128 * 40 + 255) / 256, 256>>>(Wm1, w1h, w1l, 32, 128);
    wprep_kernel<<<(4 * 9 * 32 * 40 + 255) / 256, 256>>>(Wm2, w2h, w2l, 128, 32);

    // 1. LN1 -> padded
    ln_pad_kernel<<<128, 256>>>(x, n1g, n1b, xpad);
    // 2-4. k, q (stride 2), v (stride 1)
    convT<32, 32, 2, false, false, false, false><<<dim3(128, 8, 1), 128, SM2>>>(xpad, wkh, wkl, nullptr, nullptr, k);
    convT<32, 32, 2, false, false, false, false><<<dim3(128, 8, 1), 128, SM2>>>(xpad, wqh, wql, nullptr, nullptr, q);
    convT<32, 32, 1, false, false, false, false><<<dim3(128, 32, 1), 128, SM1>>>(xpad, wvh, wvl, nullptr, nullptr, v);
    // 5-6. attention
    qk_softmax_kernel<<<1024, 256>>>(q, k, att);
    av_kernel<<<dim3(32, 64), 256>>>(att, v, ypad);
    // 7. output projection + residual(x)
    convT<32, 32, 1, true, false, true, false><<<dim3(128, 32, 1), 128, SM1>>>(ypad, woh, wol, bo, x, x1);
    // 8. LN2 -> padded
    ln_pad_kernel<<<128, 256>>>(x1, n2g, n2b, xpad);
    // 9. mixer conv1 + GELU -> padded hidden (Cout=128, 4 cout-blocks)
    convT<32, 128, 1, true, true, false, true><<<dim3(128, 32, 4), 128, SM1>>>(xpad, w1h, w1l, bm1, nullptr, hpad);
    // 10. mixer conv2 + residual(x1) -> out
    convT<128, 32, 1, true, false, true, false><<<dim3(128, 32, 1), 128, SM1>>>(hpad, w2h, w2l, bm2, x1, out);
}

// round 5
// speedup vs baseline: 2.0088x; 1.1934x over previous
#include <cuda_runtime.h>
#include <cuda_bf16.h>
#include <math.h>
#include <cstdint>

// ===========================================================================
// STCNNT cell, convs as implicit GEMM on mma.sync (HMMA bf16, fp32 accum,
// hi/lo 3-product split). Activations pre-packed as uint32 (bf16 hi | bf16 lo).
// B=4, T=32 (BT=128), C=32, H=W=64, mixer=128, n_head=8
// ===========================================================================

#define BT 128

// ---------------- device scratch ----------------
__device__ uint32_t g_xpad[BT * 32 * 66 * 66];   // packed hi/lo, padded
__device__ uint32_t g_ypad[BT * 32 * 66 * 66];
__device__ uint32_t g_hpad[BT * 128 * 66 * 66];
__device__ float g_v  [BT * 32 * 64 * 64];
__device__ float g_q  [BT * 32 * 32 * 32];
__device__ float g_k  [BT * 32 * 32 * 32];
__device__ float g_att[4 * 8 * 32 * 32];
__device__ float g_x1 [BT * 32 * 64 * 64];
#define WSTRIDE 46080   // halfs per (conv, hi|lo): max KB*9*COUT*40
__device__ __align__(16) __nv_bfloat16 g_wb[6 * 2 * WSTRIDE];

__device__ __forceinline__ float gelu_f(float v) {
    float u = 0.7978845608028654f * (v + 0.044715f * v * v * v);
    return 0.5f * v * (1.0f + tanhf(u));
}

__device__ __forceinline__ uint32_t pack_hilo(float v) {
    __nv_bfloat16 h = __float2bfloat16_rn(v);
    float hf = __bfloat162float(h);
    __nv_bfloat16 l = __float2bfloat16_rn(v - hf);
    uint16_t hb = *(uint16_t*)&h, lb = *(uint16_t*)&l;
    return (uint32_t)hb | ((uint32_t)lb << 16);
}

__device__ __forceinline__ void mma_bf16(float* c, uint32_t a0, uint32_t a1,
                                         uint32_t a2, uint32_t a3,
                                         uint32_t b0, uint32_t b1) {
    asm volatile(
        "mma.sync.aligned.m16n8k16.row.col.f32.bf16.bf16.f32 "
        "{%0,%1,%2,%3}, {%4,%5,%6,%7}, {%8,%9}, {%0,%1,%2,%3};"
        : "+f"(c[0]), "+f"(c[1]), "+f"(c[2]), "+f"(c[3])
        : "r"(a0), "r"(a1), "r"(a2), "r"(a3), "r"(b0), "r"(b1));
}

// ---------------------------------------------------------------------------
// zero 1-cell border of padded [128][CH][66][66] (packed uint32)
// ---------------------------------------------------------------------------
__global__ void zb_kernel(uint32_t* __restrict__ p, int CH) {
    int idx = blockIdx.x * blockDim.x + threadIdx.x;
    int total = 128 * CH * 260;
    if (idx >= total) return;
    int sc = idx / 260, j = idx - sc * 260;
    int yy, xx;
    if (j < 66)       { yy = 0;       xx = j; }
    else if (j < 132) { yy = 65;      xx = j - 66; }
    else if (j < 196) { yy = j - 131; xx = 0; }
    else              { yy = j - 195; xx = 65; }
    p[(size_t)sc * 4356 + yy * 66 + xx] = 0u;
}

// ---------------------------------------------------------------------------
// weight prep: fp32 [Cout][Cin][3][3] -> bf16 hi/lo planes,
// layout [ciblk][tap][cout][40] (k-slot 0..31 real, 32..39 zero pad)
// ---------------------------------------------------------------------------
__global__ void wprep_kernel(const float* __restrict__ w,
                             __nv_bfloat16* __restrict__ hi,
                             __nv_bfloat16* __restrict__ lo,
                             int CIN, int COUT) {
    int KB = CIN / 32;
    int total = KB * 9 * COUT * 40;
    int idx = blockIdx.x * blockDim.x + threadIdx.x;
    if (idx >= total) return;
    int kk = idx % 40;
    int t1 = idx / 40;
    int cout = t1 % COUT;
    int t2 = t1 / COUT;
    int tap = t2 % 9, cib = t2 / 9;
    float wv = (kk < 32) ? w[((size_t)cout * CIN + cib * 32 + kk) * 9 + tap] : 0.f;
    __nv_bfloat16 h = __float2bfloat16_rn(wv);
    __nv_bfloat16 l = __float2bfloat16_rn(wv - __bfloat162float(h));
    hi[idx] = h;
    lo[idx] = l;
}

// ---------------------------------------------------------------------------
// LayerNorm over (C,H,W)=131072 -> packed padded [n][32][66][66]. grid=128
// ---------------------------------------------------------------------------
__global__ void ln_pad_kernel(const float* __restrict__ x, const float* __restrict__ g,
                              const float* __restrict__ b, uint32_t* __restrict__ out) {
    int n = blockIdx.x;
    const float4* x4 = (const float4*)(x + (size_t)n * 131072);
    float s = 0.f, ss = 0.f;
    for (int i = threadIdx.x; i < 32768; i += 256) {
        float4 v = x4[i];
        s  += v.x + v.y + v.z + v.w;
        ss += v.x * v.x + v.y * v.y + v.z * v.z + v.w * v.w;
    }
    __shared__ float rs[8], rss[8];
    #pragma unroll
    for (int o = 16; o > 0; o >>= 1) {
        s  += __shfl_xor_sync(0xffffffffu, s, o);
        ss += __shfl_xor_sync(0xffffffffu, ss, o);
    }
    int w = threadIdx.x >> 5;
    if ((threadIdx.x & 31) == 0) { rs[w] = s; rss[w] = ss; }
    __syncthreads();
    if (threadIdx.x < 32) {
        s  = (threadIdx.x < 8) ? rs[threadIdx.x]  : 0.f;
        ss = (threadIdx.x < 8) ? rss[threadIdx.x] : 0.f;
        #pragma unroll
        for (int o = 4; o > 0; o >>= 1) {
            s  += __shfl_xor_sync(0xffffffffu, s, o);
            ss += __shfl_xor_sync(0xffffffffu, ss, o);
        }
        if (threadIdx.x == 0) { rs[0] = s; rss[0] = ss; }
    }
    __syncthreads();
    float mean = rs[0] * (1.f / 131072.f);
    float var  = rss[0] * (1.f / 131072.f) - mean * mean;
    float rstd = rsqrtf(var + 1e-5f);
    const float4* g4 = (const float4*)g;
    const float4* b4 = (const float4*)b;
    uint32_t* ob = out + (size_t)n * 32 * 4356;
    for (int i = threadIdx.x; i < 32768; i += 256) {
        float4 v = x4[i], gg = g4[i], bb = b4[i];
        int e = i * 4;
        int ci = e >> 12, rem = e & 4095;
        int y = rem >> 6, xx = rem & 63;
        uint32_t* o = ob + (size_t)ci * 4356 + (y + 1) * 66 + (xx + 1);
        o[0] = pack_hilo((v.x - mean) * rstd * gg.x + bb.x);
        o[1] = pack_hilo((v.y - mean) * rstd * gg.y + bb.y);
        o[2] = pack_hilo((v.z - mean) * rstd * gg.z + bb.z);
        o[3] = pack_hilo((v.w - mean) * rstd * gg.w + bb.w);
    }
}

// ---------------------------------------------------------------------------
// HMMA implicit-GEMM 3x3 conv. Input packed padded [n][CIN][66][66].
// grid=(128, ytiles, COUT/32), block=128 (4 warps).
// CTA: 32 couts x (NT*32) pixels. Warp: 32 couts x (NT*8) pixels.
// ---------------------------------------------------------------------------
template<int CIN, int COUT, int STRIDE, int NT, bool HASBIAS, bool DOGELU, bool RES, bool PADOUT>
__global__ void __launch_bounds__(128) convT(
    const uint32_t* __restrict__ in,
    const __nv_bfloat16* __restrict__ wph,
    const __nv_bfloat16* __restrict__ wpl,
    const float* __restrict__ bias,
    const float* __restrict__ res,
    void* __restrict__ outv) {

    constexpr int WOUT  = 64 / STRIDE;
    constexpr int RPT   = NT * 32 / WOUT;          // output rows per CTA
    constexpr int NR    = (RPT - 1) * STRIDE + 3;  // input rows needed
    constexpr int KB    = CIN / 32;
    constexpr int S_IN  = NR * 66 * 40;            // halfs per plane
    constexpr int S_W   = 9 * 32 * 40;

    extern __shared__ __align__(16) __nv_bfloat16 smem[];
    __nv_bfloat16* s_ih = smem;
    __nv_bfloat16* s_il = smem + S_IN;
    __nv_bfloat16* s_wh = smem + 2 * S_IN;
    __nv_bfloat16* s_wl = s_wh + S_W;
    uint16_t* sih16 = (uint16_t*)s_ih;
    uint16_t* sil16 = (uint16_t*)s_il;

    int n = blockIdx.x, by = blockIdx.y, cb = blockIdx.z;
    int tid = threadIdx.x, lane = tid & 31, wid = tid >> 5;
    int g = lane >> 2, tg = lane & 3;
    int row0 = by * RPT * STRIDE;

    // per-lane B-fragment base smem offsets
    int off0[NT];
    #pragma unroll
    for (int nt = 0; nt < NT; nt++) {
        int p = wid * (NT * 8) + nt * 8 + g;
        int r = p / WOUT, xx = p % WOUT;
        off0[nt] = (r * STRIDE * 66 + xx * STRIDE) * 40;
    }

    float acc[2][NT][4] = {};

    for (int cib = 0; cib < KB; cib++) {
        if (cib) __syncthreads();
        // build s_in: unpack packed hi/lo, layout [rr*66+cc][ci]
        const uint32_t* inb = in + ((size_t)n * CIN + cib * 32) * 4356 + row0 * 66;
        for (int j = tid; j < NR * 66 * 32; j += 128) {
            int ci = j / (NR * 66);
            int rem = j - ci * (NR * 66);
            uint32_t p = __ldg(inb + (size_t)ci * 4356 + rem);
            int so = rem * 40 + ci;
            sih16[so] = (uint16_t)p;
            sil16[so] = (uint16_t)(p >> 16);
        }
        // weights (pre-laid-out) -> smem
        {
            const float4* srch = (const float4*)wph;
            const float4* srcl = (const float4*)wpl;
            float4* dsth = (float4*)s_wh;
            float4* dstl = (float4*)s_wl;
            for (int i = tid; i < 1440; i += 128) {     // 9*32*40 halfs / 8
                int tap = i / 160, rem = i - tap * 160;
                int si = ((cib * 9 + tap) * COUT + cb * 32) * 5 + rem;
                dsth[i] = srch[si];
                dstl[i] = srcl[si];
            }
        }
        __syncthreads();

        #pragma unroll 3
        for (int tap = 0; tap < 9; tap++) {
            int dy = tap / 3, dx = tap - dy * 3;
            int toff = (dy * 66 + dx) * 40;
            const __nv_bfloat16* wh = s_wh + tap * 1280;
            const __nv_bfloat16* wl = s_wl + tap * 1280;
            #pragma unroll
            for (int kc = 0; kc < 2; kc++) {
                uint32_t Ah[2][4], Al[2][4];
                #pragma unroll
                for (int mt = 0; mt < 2; mt++) {
                    int a0 = (mt * 16 + g) * 40 + kc * 16 + tg * 2;
                    Ah[mt][0] = *(const uint32_t*)(wh + a0);
                    Ah[mt][1] = *(const uint32_t*)(wh + a0 + 320);
                    Ah[mt][2] = *(const uint32_t*)(wh + a0 + 8);
                    Ah[mt][3] = *(const uint32_t*)(wh + a0 + 328);
                    Al[mt][0] = *(const uint32_t*)(wl + a0);
                    Al[mt][1] = *(const uint32_t*)(wl + a0 + 320);
                    Al[mt][2] = *(const uint32_t*)(wl + a0 + 8);
                    Al[mt][3] = *(const uint32_t*)(wl + a0 + 328);
                }
                #pragma unroll
                for (int nt = 0; nt < NT; nt++) {
                    int bo = off0[nt] + toff + kc * 16 + tg * 2;
                    uint32_t bh0 = *(const uint32_t*)(s_ih + bo);
                    uint32_t bh1 = *(const uint32_t*)(s_ih + bo + 8);
                    uint32_t bl0 = *(const uint32_t*)(s_il + bo);
                    uint32_t bl1 = *(const uint32_t*)(s_il + bo + 8);
                    mma_bf16(acc[0][nt], Ah[0][0], Ah[0][1], Ah[0][2], Ah[0][3], bh0, bh1);
                    mma_bf16(acc[1][nt], Ah[1][0], Ah[1][1], Ah[1][2], Ah[1][3], bh0, bh1);
                    mma_bf16(acc[0][nt], Al[0][0], Al[0][1], Al[0][2], Al[0][3], bh0, bh1);
                    mma_bf16(acc[1][nt], Al[1][0], Al[1][1], Al[1][2], Al[1][3], bh0, bh1);
                    mma_bf16(acc[0][nt], Ah[0][0], Ah[0][1], Ah[0][2], Ah[0][3], bl0, bl1);
                    mma_bf16(acc[1][nt], Ah[1][0], Ah[1][1], Ah[1][2], Ah[1][3], bl0, bl1);
                }
            }
        }
    }

    // epilogue: C rows = couts, cols = pixels (c0,c1 x-adjacent)
    #pragma unroll
    for (int mt = 0; mt < 2; mt++) {
        int co = cb * 32 + mt * 16 + g;
        float bv0 = 0.f, bv1 = 0.f;
        if (HASBIAS) { bv0 = bias[co]; bv1 = bias[co + 8]; }
        #pragma unroll
        for (int nt = 0; nt < NT; nt++) {
            int p = wid * (NT * 8) + nt * 8 + 2 * tg;
            int r = p / WOUT, xx = p % WOUT;
            int oy = by * RPT + r;
            float v0 = acc[mt][nt][0] + bv0;
            float v1 = acc[mt][nt][1] + bv0;
            float v2 = acc[mt][nt][2] + bv1;
            float v3 = acc[mt][nt][3] + bv1;
            if (DOGELU) { v0 = gelu_f(v0); v1 = gelu_f(v1); v2 = gelu_f(v2); v3 = gelu_f(v3); }
            if (PADOUT) {
                uint32_t* o = (uint32_t*)outv + ((size_t)n * COUT + co) * 4356
                            + (oy + 1) * 66 + (xx + 1);
                o[0] = pack_hilo(v0); o[1] = pack_hilo(v1);
                o[8 * 4356] = pack_hilo(v2); o[8 * 4356 + 1] = pack_hilo(v3);
            } else {
                float* out = (float*)outv;
                size_t oi = ((size_t)n * COUT + co) * (WOUT * WOUT) + oy * WOUT + xx;
                size_t oi2 = oi + (size_t)8 * WOUT * WOUT;
                if (RES) {
                    float2 r0 = *(const float2*)(res + oi);
                    float2 r1 = *(const float2*)(res + oi2);
                    v0 += r0.x; v1 += r0.y; v2 += r1.x; v3 += r1.y;
                }
                float2 w0; w0.x = v0; w0.y = v1;
                float2 w1; w1.x = v2; w1.y = v3;
                *(float2*)(out + oi)  = w0;
                *(float2*)(out + oi2) = w1;
            }
        }
    }
}

// ---------------------------------------------------------------------------
// att = softmax(q.k/64); q,k: [BT,32,32,32]. grid=1024, block=256
// ---------------------------------------------------------------------------
__global__ void qk_softmax_kernel(const float* __restrict__ q, const float* __restrict__ k,
                                  float* __restrict__ att) {
    int bx = blockIdx.x;
    int t = bx & 31, bh = bx >> 5, h = bh & 7, b = bh >> 3;
    int lane = threadIdx.x & 31, w = threadIdx.x >> 5;
    const float4* q4 = (const float4*)(q + ((size_t)(b * 32 + t) * 32 + h * 4) * 1024);
    __shared__ float sS[32];
    #pragma unroll
    for (int si = 0; si < 4; si++) {
        int s = w * 4 + si;
        const float4* k4 = (const float4*)(k + ((size_t)(b * 32 + s) * 32 + h * 4) * 1024);
        float acc = 0.f;
        for (int d = lane; d < 1024; d += 32) {
            float4 qv = q4[d], kv = k4[d];
            acc += qv.x * kv.x + qv.y * kv.y + qv.z * kv.z + qv.w * kv.w;
        }
        #pragma unroll
        for (int o = 16; o > 0; o >>= 1) acc += __shfl_xor_sync(0xffffffffu, acc, o);
        if (lane == 0) sS[s] = acc * (1.f / 64.f);
    }
    __syncthreads();
    if (threadIdx.x < 32) {
        float v = sS[threadIdx.x];
        float m = v;
        #pragma unroll
        for (int o = 16; o > 0; o >>= 1) m = fmaxf(m, __shfl_xor_sync(0xffffffffu, m, o));
        float e = expf(v - m);
        float sum = e;
        #pragma unroll
        for (int o = 16; o > 0; o >>= 1) sum += __shfl_xor_sync(0xffffffffu, sum, o);
        att[(size_t)bx * 32 + threadIdx.x] = e / sum;
    }
}

// ---------------------------------------------------------------------------
// y = att @ v -> PACKED padded ypad. grid=(32,64), block=256
// ---------------------------------------------------------------------------
__global__ void av_kernel(const float* __restrict__ att, const float* __restrict__ v,
                          uint32_t* __restrict__ ypad) {
    int bh = blockIdx.x, b = bh >> 3, h = bh & 7;
    int d = blockIdx.y * 256 + threadIdx.x;
    int cil = d >> 12, yy = (d >> 6) & 63, xx = d & 63;
    __shared__ __align__(16) float sA[32][36];
    for (int i = threadIdx.x; i < 1024; i += 256) {
        int t = i >> 5, s = i & 31;
        sA[s][t] = att[((size_t)bh * 32 + t) * 32 + s];
    }
    __syncthreads();
    const float* vb = v + (size_t)b * 32 * 131072 + (size_t)h * 16384 + d;
    float acc[32];
    #pragma unroll
    for (int t = 0; t < 32; t++) acc[t] = 0.f;
    #pragma unroll 4
    for (int s = 0; s < 32; s++) {
        float vv = vb[(size_t)s * 131072];
        const float4* a4 = (const float4*)&sA[s][0];
        #pragma unroll
        for (int t4 = 0; t4 < 8; t4++) {
            float4 a = a4[t4];
            acc[4 * t4 + 0] += a.x * vv;
            acc[4 * t4 + 1] += a.y * vv;
            acc[4 * t4 + 2] += a.z * vv;
            acc[4 * t4 + 3] += a.w * vv;
        }
    }
    int ci = h * 4 + cil;
    size_t base = (((size_t)(b * 32) * 32 + ci) * 66 + (yy + 1)) * 66 + (xx + 1);
    #pragma unroll
    for (int t = 0; t < 32; t++) ypad[base + (size_t)t * 32 * 4356] = pack_hilo(acc[t]);
}

// ---------------------------------------------------------------------------
extern "C" void kernel_launch(void* const* d_in, const int* in_sizes, int n_in,
                              void* d_out, int out_size) {
    const float* x   = (const float*)d_in[0];
    const float* n1g = (const float*)d_in[1];
    const float* n1b = (const float*)d_in[2];
    const float* n2g = (const float*)d_in[3];
    const float* n2b = (const float*)d_in[4];
    const float* Wk  = (const float*)d_in[5];
    const float* Wq  = (const float*)d_in[6];
    const float* Wv  = (const float*)d_in[7];
    const float* Wo  = (const float*)d_in[8];
    const float* bo  = (const float*)d_in[9];
    const float* Wm1 = (const float*)d_in[10];
    const float* bm1 = (const float*)d_in[11];
    const float* Wm2 = (const float*)d_in[12];
    const float* bm2 = (const float*)d_in[13];
    float* out = (float*)d_out;

    uint32_t *xpad, *ypad, *hpad;
    float *v, *q, *k, *att, *x1;
    __nv_bfloat16* wb;
    cudaGetSymbolAddress((void**)&xpad, g_xpad);
    cudaGetSymbolAddress((void**)&ypad, g_ypad);
    cudaGetSymbolAddress((void**)&hpad, g_hpad);
    cudaGetSymbolAddress((void**)&v,    g_v);
    cudaGetSymbolAddress((void**)&q,    g_q);
    cudaGetSymbolAddress((void**)&k,    g_k);
    cudaGetSymbolAddress((void**)&att,  g_att);
    cudaGetSymbolAddress((void**)&x1,   g_x1);
    cudaGetSymbolAddress((void**)&wb,   g_wb);

    __nv_bfloat16 *wkh = wb + 0 * 2 * WSTRIDE, *wkl = wkh + WSTRIDE;
    __nv_bfloat16 *wqh = wb + 1 * 2 * WSTRIDE, *wql = wqh + WSTRIDE;
    __nv_bfloat16 *wvh = wb + 2 * 2 * WSTRIDE, *wvl = wvh + WSTRIDE;
    __nv_bfloat16 *woh = wb + 3 * 2 * WSTRIDE, *wol = woh + WSTRIDE;
    __nv_bfloat16 *w1h = wb + 4 * 2 * WSTRIDE, *w1l = w1h + WSTRIDE;
    __nv_bfloat16 *w2h = wb + 5 * 2 * WSTRIDE, *w2l = w2h + WSTRIDE;

    // dynamic smem: s1(NT=8, NR=6): (2*15840 + 2*11520)*2 = 109440
    //               s2(NT=4, NR=9): (2*23760 + 2*11520)*2 = 141120
    const int SM1 = 109440;
    const int SM2 = 141120;
    cudaFuncSetAttribute(convT<32, 32, 2, 4, false, false, false, false>,
                         cudaFuncAttributeMaxDynamicSharedMemorySize, SM2);
    cudaFuncSetAttribute(convT<32, 32, 1, 8, false, false, false, false>,
                         cudaFuncAttributeMaxDynamicSharedMemorySize, SM1);
    cudaFuncSetAttribute(convT<32, 32, 1, 8, true, false, true, false>,
                         cudaFuncAttributeMaxDynamicSharedMemorySize, SM1);
    cudaFuncSetAttribute(convT<32, 128, 1, 8, true, true, false, true>,
                         cudaFuncAttributeMaxDynamicSharedMemorySize, SM1);
    cudaFuncSetAttribute(convT<128, 32, 1, 8, true, false, true, false>,
                         cudaFuncAttributeMaxDynamicSharedMemorySize, SM1);

    // border zeroing + weight prep
    zb_kernel<<<(128 * 32 * 260 + 255) / 256, 256>>>(xpad, 32);
    zb_kernel<<<(128 * 32 * 260 + 255) / 256, 256>>>(ypad, 32);
    zb_kernel<<<(128 * 128 * 260 + 255) / 256, 256>>>(hpad, 128);
    wprep_kernel<<<(9 * 32 * 40 + 255) / 256, 256>>>(Wk,  wkh, wkl, 32, 32);
    wprep_kernel<<<(9 * 32 * 40 + 255) / 256, 256>>>(Wq,  wqh, wql, 32, 32);
    wprep_kernel<<<(9 * 32 * 40 + 255) / 256, 256>>>(Wv,  wvh, wvl, 32, 32);
    wprep_kernel<<<(9 * 32 * 40 + 255) / 256, 256>>>(Wo,  woh, wol, 32, 32);
    wprep_kernel<<<(9 * 128 * 40 + 255) / 256, 256>>>(Wm1, w1h, w1l, 32, 128);
    wprep_kernel<<<(4 * 9 * 32 * 40 + 255) / 256, 256>>>(Wm2, w2h, w2l, 128, 32);

    // 1. LN1 -> packed padded
    ln_pad_kernel<<<128, 256>>>(x, n1g, n1b, xpad);
    // 2-4. k, q (stride 2), v (stride 1)
    convT<32, 32, 2, 4, false, false, false, false><<<dim3(128, 8, 1), 128, SM2>>>(xpad, wkh, wkl, nullptr, nullptr, k);
    convT<32, 32, 2, 4, false, false, false, false><<<dim3(128, 8, 1), 128, SM2>>>(xpad, wqh, wql, nullptr, nullptr, q);
    convT<32, 32, 1, 8, false, false, false, false><<<dim3(128, 16, 1), 128, SM1>>>(xpad, wvh, wvl, nullptr, nullptr, v);
    // 5-6. attention
    qk_softmax_kernel<<<1024, 256>>>(q, k, att);
    av_kernel<<<dim3(32, 64), 256>>>(att, v, ypad);
    // 7. output projection + residual(x)
    convT<32, 32, 1, 8, true, false, true, false><<<dim3(128, 16, 1), 128, SM1>>>(ypad, woh, wol, bo, x, x1);
    // 8. LN2 -> packed padded
    ln_pad_kernel<<<128, 256>>>(x1, n2g, n2b, xpad);
    // 9. mixer conv1 + GELU -> packed padded hidden (4 cout blocks)
    convT<32, 128, 1, 8, true, true, false, true><<<dim3(128, 16, 4), 128, SM1>>>(xpad, w1h, w1l, bm1, nullptr, hpad);
    // 10. mixer conv2 + residual(x1) -> out
    convT<128, 32, 1, 8, true, false, true, false><<<dim3(128, 16, 1), 128, SM1>>>(hpad, w2h, w2l, bm2, x1, out);
}

// round 6
// speedup vs baseline: 3.0047x; 1.4957x over previous
#include <cuda_runtime.h>
#include <cuda_bf16.h>
#include <math.h>
#include <cstdint>

// ===========================================================================
// STCNNT cell, convs as implicit GEMM on mma.sync (HMMA bf16, fp32 accum,
// hi/lo 3-product split). Activations packed uint32 (bf16 hi | bf16 lo).
// 256-thread CTAs, packed+swizzled smem input plane.
// B=4, T=32 (BT=128), C=32, H=W=64, mixer=128, n_head=8
// ===========================================================================

#define BT 128

// ---------------- device scratch ----------------
__device__ uint32_t g_xpad[BT * 32 * 66 * 66];   // packed hi/lo, padded, [n][ci][66][66]
__device__ uint32_t g_ypad[BT * 32 * 66 * 66];
__device__ uint32_t g_hpad[BT * 128 * 66 * 66];
__device__ float g_v  [BT * 32 * 64 * 64];
__device__ float g_q  [BT * 32 * 32 * 32];
__device__ float g_k  [BT * 32 * 32 * 32];
__device__ float g_att[4 * 8 * 32 * 32];
__device__ float g_x1 [BT * 32 * 64 * 64];
#define WSTRIDE 46080   // halfs per (conv, hi|lo): max KB*9*COUT*40
__device__ __align__(16) __nv_bfloat16 g_wb[6 * 2 * WSTRIDE];

__device__ __forceinline__ float gelu_f(float v) {
    float u = 0.7978845608028654f * (v + 0.044715f * v * v * v);
    return 0.5f * v * (1.0f + tanhf(u));
}

__device__ __forceinline__ uint32_t pack_hilo(float v) {
    __nv_bfloat16 h = __float2bfloat16_rn(v);
    float hf = __bfloat162float(h);
    __nv_bfloat16 l = __float2bfloat16_rn(v - hf);
    uint16_t hb = *(uint16_t*)&h, lb = *(uint16_t*)&l;
    return (uint32_t)hb | ((uint32_t)lb << 16);
}

__device__ __forceinline__ void mma_bf16(float* c, uint32_t a0, uint32_t a1,
                                         uint32_t a2, uint32_t a3,
                                         uint32_t b0, uint32_t b1) {
    asm volatile(
        "mma.sync.aligned.m16n8k16.row.col.f32.bf16.bf16.f32 "
        "{%0,%1,%2,%3}, {%4,%5,%6,%7}, {%8,%9}, {%0,%1,%2,%3};"
        : "+f"(c[0]), "+f"(c[1]), "+f"(c[2]), "+f"(c[3])
        : "r"(a0), "r"(a1), "r"(a2), "r"(a3), "r"(b0), "r"(b1));
}

// ---------------------------------------------------------------------------
// zero 1-cell border of padded [128][CH][66][66] (packed uint32)
// ---------------------------------------------------------------------------
__global__ void zb_kernel(uint32_t* __restrict__ p, int CH) {
    int idx = blockIdx.x * blockDim.x + threadIdx.x;
    int total = 128 * CH * 260;
    if (idx >= total) return;
    int sc = idx / 260, j = idx - sc * 260;
    int yy, xx;
    if (j < 66)       { yy = 0;       xx = j; }
    else if (j < 132) { yy = 65;      xx = j - 66; }
    else if (j < 196) { yy = j - 131; xx = 0; }
    else              { yy = j - 195; xx = 65; }
    p[(size_t)sc * 4356 + yy * 66 + xx] = 0u;
}

// ---------------------------------------------------------------------------
// weight prep: fp32 [Cout][Cin][3][3] -> bf16 hi/lo planes,
// layout [ciblk][tap][cout][40] (k-slot 0..31 real, 32..39 zero pad)
// ---------------------------------------------------------------------------
__global__ void wprep_kernel(const float* __restrict__ w,
                             __nv_bfloat16* __restrict__ hi,
                             __nv_bfloat16* __restrict__ lo,
                             int CIN, int COUT) {
    int KB = CIN / 32;
    int total = KB * 9 * COUT * 40;
    int idx = blockIdx.x * blockDim.x + threadIdx.x;
    if (idx >= total) return;
    int kk = idx % 40;
    int t1 = idx / 40;
    int cout = t1 % COUT;
    int t2 = t1 / COUT;
    int tap = t2 % 9, cib = t2 / 9;
    float wv = (kk < 32) ? w[((size_t)cout * CIN + cib * 32 + kk) * 9 + tap] : 0.f;
    __nv_bfloat16 h = __float2bfloat16_rn(wv);
    __nv_bfloat16 l = __float2bfloat16_rn(wv - __bfloat162float(h));
    hi[idx] = h;
    lo[idx] = l;
}

// ---------------------------------------------------------------------------
// LayerNorm over (C,H,W)=131072 -> packed padded [n][32][66][66]. grid=128
// ---------------------------------------------------------------------------
__global__ void ln_pad_kernel(const float* __restrict__ x, const float* __restrict__ g,
                              const float* __restrict__ b, uint32_t* __restrict__ out) {
    int n = blockIdx.x;
    const float4* x4 = (const float4*)(x + (size_t)n * 131072);
    float s = 0.f, ss = 0.f;
    for (int i = threadIdx.x; i < 32768; i += 256) {
        float4 v = x4[i];
        s  += v.x + v.y + v.z + v.w;
        ss += v.x * v.x + v.y * v.y + v.z * v.z + v.w * v.w;
    }
    __shared__ float rs[8], rss[8];
    #pragma unroll
    for (int o = 16; o > 0; o >>= 1) {
        s  += __shfl_xor_sync(0xffffffffu, s, o);
        ss += __shfl_xor_sync(0xffffffffu, ss, o);
    }
    int w = threadIdx.x >> 5;
    if ((threadIdx.x & 31) == 0) { rs[w] = s; rss[w] = ss; }
    __syncthreads();
    if (threadIdx.x < 32) {
        s  = (threadIdx.x < 8) ? rs[threadIdx.x]  : 0.f;
        ss = (threadIdx.x < 8) ? rss[threadIdx.x] : 0.f;
        #pragma unroll
        for (int o = 4; o > 0; o >>= 1) {
            s  += __shfl_xor_sync(0xffffffffu, s, o);
            ss += __shfl_xor_sync(0xffffffffu, ss, o);
        }
        if (threadIdx.x == 0) { rs[0] = s; rss[0] = ss; }
    }
    __syncthreads();
    float mean = rs[0] * (1.f / 131072.f);
    float var  = rss[0] * (1.f / 131072.f) - mean * mean;
    float rstd = rsqrtf(var + 1e-5f);
    const float4* g4 = (const float4*)g;
    const float4* b4 = (const float4*)b;
    uint32_t* ob = out + (size_t)n * 32 * 4356;
    for (int i = threadIdx.x; i < 32768; i += 256) {
        float4 v = x4[i], gg = g4[i], bb = b4[i];
        int e = i * 4;
        int ci = e >> 12, rem = e & 4095;
        int y = rem >> 6, xx = rem & 63;
        uint32_t* o = ob + (size_t)ci * 4356 + (y + 1) * 66 + (xx + 1);
        o[0] = pack_hilo((v.x - mean) * rstd * gg.x + bb.x);
        o[1] = pack_hilo((v.y - mean) * rstd * gg.y + bb.y);
        o[2] = pack_hilo((v.z - mean) * rstd * gg.z + bb.z);
        o[3] = pack_hilo((v.w - mean) * rstd * gg.w + bb.w);
    }
}

// ---------------------------------------------------------------------------
// HMMA implicit-GEMM 3x3 conv. Input packed padded [n][CIN][66][66].
// grid=(128, ytiles, COUT/32), block=256 (8 warps).
// CTA: 32 couts x (NT*64) pixels. Warp: 32 couts x (NT*8) pixels.
// smem input plane: packed uint32 [rem][32 ci], XOR-swizzled banks.
// ---------------------------------------------------------------------------
template<int CIN, int COUT, int STRIDE, int NT, bool HASBIAS, bool DOGELU, bool RES, bool PADOUT>
__global__ void __launch_bounds__(256) convT(
    const uint32_t* __restrict__ in,
    const __nv_bfloat16* __restrict__ wph,
    const __nv_bfloat16* __restrict__ wpl,
    const float* __restrict__ bias,
    const float* __restrict__ res,
    void* __restrict__ outv) {

    constexpr int WOUT  = 64 / STRIDE;
    constexpr int PIX   = NT * 64;                 // pixels per CTA (8 warps)
    constexpr int RPT   = PIX / WOUT;              // output rows per CTA
    constexpr int NR    = (RPT - 1) * STRIDE + 3;  // input rows needed
    constexpr int KB    = CIN / 32;
    constexpr int S_INW = NR * 66 * 32;            // packed words
    constexpr int S_W   = 9 * 32 * 40;             // halfs per weight plane

    extern __shared__ __align__(16) uint32_t smem[];
    uint32_t* s_pk = smem;
    __nv_bfloat16* s_wh = (__nv_bfloat16*)(s_pk + S_INW);
    __nv_bfloat16* s_wl = s_wh + S_W;

    int n = blockIdx.x, by = blockIdx.y, cb = blockIdx.z;
    int tid = threadIdx.x, lane = tid & 31, wid = tid >> 5;
    int g = lane >> 2, tg = lane & 3;
    int row0 = by * RPT * STRIDE;

    // per-lane B base rem (pixel -> input row/col)
    int off0[NT];
    #pragma unroll
    for (int nt = 0; nt < NT; nt++) {
        int p = wid * (NT * 8) + nt * 8 + g;
        int r = p / WOUT, xx = p % WOUT;
        off0[nt] = (r * STRIDE) * 66 + xx * STRIDE;
    }

    float acc[2][NT][4] = {};

    for (int cib = 0; cib < KB; cib++) {
        if (cib) __syncthreads();
        // build packed plane: [rem][ci^((rem&3)<<3)]
        const uint32_t* inb = in + ((size_t)n * CIN + cib * 32) * 4356 + row0 * 66;
        for (int j = tid; j < 32 * (NR * 66 / 2); j += 256) {
            int ci = j & 31, rem2 = j >> 5;
            uint2 p = *(const uint2*)(inb + (size_t)ci * 4356 + 2 * rem2);
            int r0 = 2 * rem2, r1 = r0 + 1;
            s_pk[r0 * 32 + (ci ^ ((r0 & 3) << 3))] = p.x;
            s_pk[r1 * 32 + (ci ^ ((r1 & 3) << 3))] = p.y;
        }
        // weights (pre-laid-out) -> smem
        {
            const float4* srch = (const float4*)wph;
            const float4* srcl = (const float4*)wpl;
            float4* dsth = (float4*)s_wh;
            float4* dstl = (float4*)s_wl;
            for (int i = tid; i < 1440; i += 256) {     // 9*32*40 halfs / 8
                int tap = i / 160, rem = i - tap * 160;
                int si = ((cib * 9 + tap) * COUT + cb * 32) * 5 + rem;
                dsth[i] = srch[si];
                dstl[i] = srcl[si];
            }
        }
        __syncthreads();

        #pragma unroll 3
        for (int tap = 0; tap < 9; tap++) {
            int dy = tap / 3, dx = tap - dy * 3;
            int drem = dy * 66 + dx;
            const __nv_bfloat16* wh = s_wh + tap * 1280;
            const __nv_bfloat16* wl = s_wl + tap * 1280;
            #pragma unroll
            for (int kc = 0; kc < 2; kc++) {
                uint32_t Ah[2][4], Al[2][4];
                #pragma unroll
                for (int mt = 0; mt < 2; mt++) {
                    int a0 = (mt * 16 + g) * 40 + kc * 16 + tg * 2;
                    Ah[mt][0] = *(const uint32_t*)(wh + a0);
                    Ah[mt][1] = *(const uint32_t*)(wh + a0 + 320);
                    Ah[mt][2] = *(const uint32_t*)(wh + a0 + 8);
                    Ah[mt][3] = *(const uint32_t*)(wh + a0 + 328);
                    Al[mt][0] = *(const uint32_t*)(wl + a0);
                    Al[mt][1] = *(const uint32_t*)(wl + a0 + 320);
                    Al[mt][2] = *(const uint32_t*)(wl + a0 + 8);
                    Al[mt][3] = *(const uint32_t*)(wl + a0 + 328);
                }
                int ci = kc * 16 + 2 * tg;
                #pragma unroll
                for (int nt = 0; nt < NT; nt++) {
                    int rem = off0[nt] + drem;
                    int base = rem * 32, msk = (rem & 3) << 3;
                    uint2 q0 = *(const uint2*)(s_pk + base + (ci ^ msk));
                    uint2 q1 = *(const uint2*)(s_pk + base + ((ci + 8) ^ msk));
                    uint32_t bh0 = __byte_perm(q0.x, q0.y, 0x5410);
                    uint32_t bl0 = __byte_perm(q0.x, q0.y, 0x7632);
                    uint32_t bh1 = __byte_perm(q1.x, q1.y, 0x5410);
                    uint32_t bl1 = __byte_perm(q1.x, q1.y, 0x7632);
                    mma_bf16(acc[0][nt], Ah[0][0], Ah[0][1], Ah[0][2], Ah[0][3], bh0, bh1);
                    mma_bf16(acc[1][nt], Ah[1][0], Ah[1][1], Ah[1][2], Ah[1][3], bh0, bh1);
                    mma_bf16(acc[0][nt], Al[0][0], Al[0][1], Al[0][2], Al[0][3], bh0, bh1);
                    mma_bf16(acc[1][nt], Al[1][0], Al[1][1], Al[1][2], Al[1][3], bh0, bh1);
                    mma_bf16(acc[0][nt], Ah[0][0], Ah[0][1], Ah[0][2], Ah[0][3], bl0, bl1);
                    mma_bf16(acc[1][nt], Ah[1][0], Ah[1][1], Ah[1][2], Ah[1][3], bl0, bl1);
                }
            }
        }
    }

    // epilogue
    #pragma unroll
    for (int mt = 0; mt < 2; mt++) {
        int co = cb * 32 + mt * 16 + g;
        float bv0 = 0.f, bv1 = 0.f;
        if (HASBIAS) { bv0 = bias[co]; bv1 = bias[co + 8]; }
        #pragma unroll
        for (int nt = 0; nt < NT; nt++) {
            int p = wid * (NT * 8) + nt * 8 + 2 * tg;
            int r = p / WOUT, xx = p % WOUT;
            int oy = by * RPT + r;
            float v0 = acc[mt][nt][0] + bv0;
            float v1 = acc[mt][nt][1] + bv0;
            float v2 = acc[mt][nt][2] + bv1;
            float v3 = acc[mt][nt][3] + bv1;
            if (DOGELU) { v0 = gelu_f(v0); v1 = gelu_f(v1); v2 = gelu_f(v2); v3 = gelu_f(v3); }
            if (PADOUT) {
                uint32_t* o = (uint32_t*)outv + ((size_t)n * COUT + co) * 4356
                            + (oy + 1) * 66 + (xx + 1);
                o[0] = pack_hilo(v0); o[1] = pack_hilo(v1);
                o[8 * 4356] = pack_hilo(v2); o[8 * 4356 + 1] = pack_hilo(v3);
            } else {
                float* out = (float*)outv;
                size_t oi = ((size_t)n * COUT + co) * (WOUT * WOUT) + oy * WOUT + xx;
                size_t oi2 = oi + (size_t)8 * WOUT * WOUT;
                if (RES) {
                    float2 r0 = *(const float2*)(res + oi);
                    float2 r1 = *(const float2*)(res + oi2);
                    v0 += r0.x; v1 += r0.y; v2 += r1.x; v3 += r1.y;
                }
                float2 w0; w0.x = v0; w0.y = v1;
                float2 w1; w1.x = v2; w1.y = v3;
                *(float2*)(out + oi)  = w0;
                *(float2*)(out + oi2) = w1;
            }
        }
    }
}

// ---------------------------------------------------------------------------
// att = softmax(q.k/64); q,k: [BT,32,32,32]. grid=1024, block=256
// ---------------------------------------------------------------------------
__global__ void qk_softmax_kernel(const float* __restrict__ q, const float* __restrict__ k,
                                  float* __restrict__ att) {
    int bx = blockIdx.x;
    int t = bx & 31, bh = bx >> 5, h = bh & 7, b = bh >> 3;
    int lane = threadIdx.x & 31, w = threadIdx.x >> 5;
    const float4* q4 = (const float4*)(q + ((size_t)(b * 32 + t) * 32 + h * 4) * 1024);
    __shared__ float sS[32];
    #pragma unroll
    for (int si = 0; si < 4; si++) {
        int s = w * 4 + si;
        const float4* k4 = (const float4*)(k + ((size_t)(b * 32 + s) * 32 + h * 4) * 1024);
        float acc = 0.f;
        for (int d = lane; d < 1024; d += 32) {
            float4 qv = q4[d], kv = k4[d];
            acc += qv.x * kv.x + qv.y * kv.y + qv.z * kv.z + qv.w * kv.w;
        }
        #pragma unroll
        for (int o = 16; o > 0; o >>= 1) acc += __shfl_xor_sync(0xffffffffu, acc, o);
        if (lane == 0) sS[s] = acc * (1.f / 64.f);
    }
    __syncthreads();
    if (threadIdx.x < 32) {
        float v = sS[threadIdx.x];
        float m = v;
        #pragma unroll
        for (int o = 16; o > 0; o >>= 1) m = fmaxf(m, __shfl_xor_sync(0xffffffffu, m, o));
        float e = expf(v - m);
        float sum = e;
        #pragma unroll
        for (int o = 16; o > 0; o >>= 1) sum += __shfl_xor_sync(0xffffffffu, sum, o);
        att[(size_t)bx * 32 + threadIdx.x] = e / sum;
    }
}

// ---------------------------------------------------------------------------
// y = att @ v -> PACKED padded ypad. grid=(32,64), block=256
// ---------------------------------------------------------------------------
__global__ void av_kernel(const float* __restrict__ att, const float* __restrict__ v,
                          uint32_t* __restrict__ ypad) {
    int bh = blockIdx.x, b = bh >> 3, h = bh & 7;
    int d = blockIdx.y * 256 + threadIdx.x;
    int cil = d >> 12, yy = (d >> 6) & 63, xx = d & 63;
    __shared__ __align__(16) float sA[32][36];
    for (int i = threadIdx.x; i < 1024; i += 256) {
        int t = i >> 5, s = i & 31;
        sA[s][t] = att[((size_t)bh * 32 + t) * 32 + s];
    }
    __syncthreads();
    const float* vb = v + (size_t)b * 32 * 131072 + (size_t)h * 16384 + d;
    float acc[32];
    #pragma unroll
    for (int t = 0; t < 32; t++) acc[t] = 0.f;
    #pragma unroll 4
    for (int s = 0; s < 32; s++) {
        float vv = vb[(size_t)s * 131072];
        const float4* a4 = (const float4*)&sA[s][0];
        #pragma unroll
        for (int t4 = 0; t4 < 8; t4++) {
            float4 a = a4[t4];
            acc[4 * t4 + 0] += a.x * vv;
            acc[4 * t4 + 1] += a.y * vv;
            acc[4 * t4 + 2] += a.z * vv;
            acc[4 * t4 + 3] += a.w * vv;
        }
    }
    int ci = h * 4 + cil;
    size_t base = (((size_t)(b * 32) * 32 + ci) * 66 + (yy + 1)) * 66 + (xx + 1);
    #pragma unroll
    for (int t = 0; t < 32; t++) ypad[base + (size_t)t * 32 * 4356] = pack_hilo(acc[t]);
}

// ---------------------------------------------------------------------------
extern "C" void kernel_launch(void* const* d_in, const int* in_sizes, int n_in,
                              void* d_out, int out_size) {
    const float* x   = (const float*)d_in[0];
    const float* n1g = (const float*)d_in[1];
    const float* n1b = (const float*)d_in[2];
    const float* n2g = (const float*)d_in[3];
    const float* n2b = (const float*)d_in[4];
    const float* Wk  = (const float*)d_in[5];
    const float* Wq  = (const float*)d_in[6];
    const float* Wv  = (const float*)d_in[7];
    const float* Wo  = (const float*)d_in[8];
    const float* bo  = (const float*)d_in[9];
    const float* Wm1 = (const float*)d_in[10];
    const float* bm1 = (const float*)d_in[11];
    const float* Wm2 = (const float*)d_in[12];
    const float* bm2 = (const float*)d_in[13];
    float* out = (float*)d_out;

    uint32_t *xpad, *ypad, *hpad;
    float *v, *q, *k, *att, *x1;
    __nv_bfloat16* wb;
    cudaGetSymbolAddress((void**)&xpad, g_xpad);
    cudaGetSymbolAddress((void**)&ypad, g_ypad);
    cudaGetSymbolAddress((void**)&hpad, g_hpad);
    cudaGetSymbolAddress((void**)&v,    g_v);
    cudaGetSymbolAddress((void**)&q,    g_q);
    cudaGetSymbolAddress((void**)&k,    g_k);
    cudaGetSymbolAddress((void**)&att,  g_att);
    cudaGetSymbolAddress((void**)&x1,   g_x1);
    cudaGetSymbolAddress((void**)&wb,   g_wb);

    __nv_bfloat16 *wkh = wb + 0 * 2 * WSTRIDE, *wkl = wkh + WSTRIDE;
    __nv_bfloat16 *wqh = wb + 1 * 2 * WSTRIDE, *wql = wqh + WSTRIDE;
    __nv_bfloat16 *wvh = wb + 2 * 2 * WSTRIDE, *wvl = wvh + WSTRIDE;
    __nv_bfloat16 *woh = wb + 3 * 2 * WSTRIDE, *wol = woh + WSTRIDE;
    __nv_bfloat16 *w1h = wb + 4 * 2 * WSTRIDE, *w1l = w1h + WSTRIDE;
    __nv_bfloat16 *w2h = wb + 5 * 2 * WSTRIDE, *w2l = w2h + WSTRIDE;

    // dynamic smem: s1 (NT=4, NR=6): 6*66*32*4 + 2*9*32*40*2 = 96768
    //               s2 (NT=2, NR=9): 9*66*32*4 + 46080      = 122112
    const int SM1 = 96768;
    const int SM2 = 122112;
    cudaFuncSetAttribute(convT<32, 32, 2, 2, false, false, false, false>,
                         cudaFuncAttributeMaxDynamicSharedMemorySize, SM2);
    cudaFuncSetAttribute(convT<32, 32, 1, 4, false, false, false, false>,
                         cudaFuncAttributeMaxDynamicSharedMemorySize, SM1);
    cudaFuncSetAttribute(convT<32, 32, 1, 4, true, false, true, false>,
                         cudaFuncAttributeMaxDynamicSharedMemorySize, SM1);
    cudaFuncSetAttribute(convT<32, 128, 1, 4, true, true, false, true>,
                         cudaFuncAttributeMaxDynamicSharedMemorySize, SM1);
    cudaFuncSetAttribute(convT<128, 32, 1, 4, true, false, true, false>,
                         cudaFuncAttributeMaxDynamicSharedMemorySize, SM1);

    // --- ordered so ncu (-s 5 -c 1) captures conv_v at launch #5 ---
    zb_kernel<<<(128 * 32 * 260 + 255) / 256, 256>>>(xpad, 32);                    // 0
    wprep_kernel<<<(9 * 32 * 40 + 255) / 256, 256>>>(Wv,  wvh, wvl, 32, 32);       // 1
    ln_pad_kernel<<<128, 256>>>(x, n1g, n1b, xpad);                                // 2
    wprep_kernel<<<(9 * 32 * 40 + 255) / 256, 256>>>(Wk,  wkh, wkl, 32, 32);       // 3
    wprep_kernel<<<(9 * 32 * 40 + 255) / 256, 256>>>(Wq,  wqh, wql, 32, 32);       // 4
    convT<32, 32, 1, 4, false, false, false, false><<<dim3(128, 16, 1), 256, SM1>>>(xpad, wvh, wvl, nullptr, nullptr, v);   // 5
    convT<32, 32, 2, 2, false, false, false, false><<<dim3(128, 8, 1), 256, SM2>>>(xpad, wkh, wkl, nullptr, nullptr, k);    // 6
    convT<32, 32, 2, 2, false, false, false, false><<<dim3(128, 8, 1), 256, SM2>>>(xpad, wqh, wql, nullptr, nullptr, q);    // 7
    zb_kernel<<<(128 * 32 * 260 + 255) / 256, 256>>>(ypad, 32);                    // 8
    qk_softmax_kernel<<<1024, 256>>>(q, k, att);                                   // 9
    av_kernel<<<dim3(32, 64), 256>>>(att, v, ypad);                                // 10
    wprep_kernel<<<(9 * 32 * 40 + 255) / 256, 256>>>(Wo,  woh, wol, 32, 32);       // 11
    convT<32, 32, 1, 4, true, false, true, false><<<dim3(128, 16, 1), 256, SM1>>>(ypad, woh, wol, bo, x, x1);               // 12
    ln_pad_kernel<<<128, 256>>>(x1, n2g, n2b, xpad);                               // 13
    wprep_kernel<<<(9 * 128 * 40 + 255) / 256, 256>>>(Wm1, w1h, w1l, 32, 128);     // 14
    zb_kernel<<<(128 * 128 * 260 + 255) / 256, 256>>>(hpad, 128);                  // 15
    convT<32, 128, 1, 4, true, true, false, true><<<dim3(128, 16, 4), 256, SM1>>>(xpad, w1h, w1l, bm1, nullptr, hpad);      // 16
    wprep_kernel<<<(4 * 9 * 32 * 40 + 255) / 256, 256>>>(Wm2, w2h, w2l, 128, 32);  // 17
    convT<128, 32, 1, 4, true, false, true, false><<<dim3(128, 16, 1), 256, SM1>>>(hpad, w2h, w2l, bm2, x1, out);           // 18
}

// round 7
// speedup vs baseline: 3.4560x; 1.1502x over previous
#include <cuda_runtime.h>
#include <cuda_bf16.h>
#include <math.h>
#include <cstdint>

// ===========================================================================
// STCNNT cell, convs as implicit GEMM on mma.sync (HMMA bf16, fp32 accum,
// hi/lo 3-product split). Activations CHANNEL-LAST packed uint32 (hi|lo):
// [n][row][col][ci] -> smem builds are contiguous cp.async copies.
// B=4, T=32 (BT=128), C=32, H=W=64, mixer=128, n_head=8
// ===========================================================================

#define BT 128

// ---------------- device scratch ----------------
__device__ uint32_t g_xpad[BT * 66 * 66 * 32];    // packed, padded, channel-last
__device__ uint32_t g_ypad[BT * 66 * 66 * 32];
__device__ uint32_t g_hpad[BT * 66 * 66 * 128];
__device__ float g_v  [BT * 64 * 64 * 32];        // channel-last fp32
__device__ float g_q  [BT * 32 * 32 * 32];        // standard [n][ci][y][x]
__device__ float g_k  [BT * 32 * 32 * 32];
__device__ float g_att[4 * 8 * 32 * 32];
__device__ float g_x1 [BT * 32 * 64 * 64];        // standard
#define WSTRIDE 46080   // halfs per (conv, hi|lo): max KB*9*COUT*40
__device__ __align__(16) __nv_bfloat16 g_wb[6 * 2 * WSTRIDE];

__device__ __forceinline__ float gelu_f(float v) {
    float u = 0.7978845608028654f * (v + 0.044715f * v * v * v);
    return 0.5f * v * (1.0f + tanhf(u));
}

__device__ __forceinline__ uint32_t pack_hilo(float v) {
    __nv_bfloat16 h = __float2bfloat16_rn(v);
    float hf = __bfloat162float(h);
    __nv_bfloat16 l = __float2bfloat16_rn(v - hf);
    uint16_t hb = *(uint16_t*)&h, lb = *(uint16_t*)&l;
    return (uint32_t)hb | ((uint32_t)lb << 16);
}

__device__ __forceinline__ uint32_t smem_to_u32(const void* p) {
    uint32_t a;
    asm("{ .reg .u64 t; cvta.to.shared.u64 t, %1; cvt.u32.u64 %0, t; }" : "=r"(a) : "l"(p));
    return a;
}

__device__ __forceinline__ void mma_bf16(float* c, uint32_t a0, uint32_t a1,
                                         uint32_t a2, uint32_t a3,
                                         uint32_t b0, uint32_t b1) {
    asm volatile(
        "mma.sync.aligned.m16n8k16.row.col.f32.bf16.bf16.f32 "
        "{%0,%1,%2,%3}, {%4,%5,%6,%7}, {%8,%9}, {%0,%1,%2,%3};"
        : "+f"(c[0]), "+f"(c[1]), "+f"(c[2]), "+f"(c[3])
        : "r"(a0), "r"(a1), "r"(a2), "r"(a3), "r"(b0), "r"(b1));
}

// ---------------------------------------------------------------------------
// zero 1-cell border of padded channel-last [128][66][66][CW]
// ---------------------------------------------------------------------------
__global__ void zb_kernel(uint32_t* __restrict__ p, int CW) {
    int idx = blockIdx.x * blockDim.x + threadIdx.x;
    int total = 128 * 260 * CW;
    if (idx >= total) return;
    int ci = idx % CW;
    int t1 = idx / CW;
    int j = t1 % 260, n = t1 / 260;
    int yy, xx;
    if (j < 66)       { yy = 0;       xx = j; }
    else if (j < 132) { yy = 65;      xx = j - 66; }
    else if (j < 196) { yy = j - 131; xx = 0; }
    else              { yy = j - 195; xx = 65; }
    p[((size_t)n * 4356 + yy * 66 + xx) * CW + ci] = 0u;
}

// ---------------------------------------------------------------------------
// weight prep: fp32 [Cout][Cin][3][3] -> bf16 hi/lo planes,
// layout [ciblk][tap][cout][40] (k-slot 0..31 real, 32..39 zero pad)
// ---------------------------------------------------------------------------
__global__ void wprep_kernel(const float* __restrict__ w,
                             __nv_bfloat16* __restrict__ hi,
                             __nv_bfloat16* __restrict__ lo,
                             int CIN, int COUT) {
    int KB = CIN / 32;
    int total = KB * 9 * COUT * 40;
    int idx = blockIdx.x * blockDim.x + threadIdx.x;
    if (idx >= total) return;
    int kk = idx % 40;
    int t1 = idx / 40;
    int cout = t1 % COUT;
    int t2 = t1 / COUT;
    int tap = t2 % 9, cib = t2 / 9;
    float wv = (kk < 32) ? w[((size_t)cout * CIN + cib * 32 + kk) * 9 + tap] : 0.f;
    __nv_bfloat16 h = __float2bfloat16_rn(wv);
    __nv_bfloat16 l = __float2bfloat16_rn(wv - __bfloat162float(h));
    hi[idx] = h;
    lo[idx] = l;
}

// ---------------------------------------------------------------------------
// LayerNorm over (C,H,W)=131072 -> packed padded CHANNEL-LAST [n][66][66][32]
// grid=128, block=256. smem transpose keeps reads and writes coalesced.
// ---------------------------------------------------------------------------
__global__ void ln_pad_kernel(const float* __restrict__ x, const float* __restrict__ g,
                              const float* __restrict__ b, uint32_t* __restrict__ out) {
    int n = blockIdx.x;
    const float* xb = x + (size_t)n * 131072;
    const float4* x4 = (const float4*)xb;
    float s = 0.f, ss = 0.f;
    for (int i = threadIdx.x; i < 32768; i += 256) {
        float4 v = x4[i];
        s  += v.x + v.y + v.z + v.w;
        ss += v.x * v.x + v.y * v.y + v.z * v.z + v.w * v.w;
    }
    __shared__ float rs[8], rss[8];
    #pragma unroll
    for (int o = 16; o > 0; o >>= 1) {
        s  += __shfl_xor_sync(0xffffffffu, s, o);
        ss += __shfl_xor_sync(0xffffffffu, ss, o);
    }
    int wrp = threadIdx.x >> 5, lane = threadIdx.x & 31;
    if (lane == 0) { rs[wrp] = s; rss[wrp] = ss; }
    __syncthreads();
    if (threadIdx.x < 32) {
        s  = (threadIdx.x < 8) ? rs[threadIdx.x]  : 0.f;
        ss = (threadIdx.x < 8) ? rss[threadIdx.x] : 0.f;
        #pragma unroll
        for (int o = 4; o > 0; o >>= 1) {
            s  += __shfl_xor_sync(0xffffffffu, s, o);
            ss += __shfl_xor_sync(0xffffffffu, ss, o);
        }
        if (threadIdx.x == 0) { rs[0] = s; rss[0] = ss; }
    }
    __syncthreads();
    float mean = rs[0] * (1.f / 131072.f);
    float var  = rss[0] * (1.f / 131072.f) - mean * mean;
    float rstd = rsqrtf(var + 1e-5f);

    __shared__ float tile[32][33];
    uint32_t* ob = out + (size_t)n * 4356 * 32;
    for (int t0 = 0; t0 < 4096; t0 += 32) {
        __syncthreads();
        #pragma unroll
        for (int cc = 0; cc < 4; cc++) {
            int ci = wrp * 4 + cc;
            int px = t0 + lane;
            size_t e = (size_t)ci * 4096 + px;
            tile[ci][lane] = (xb[e] - mean) * rstd * __ldg(g + e) + __ldg(b + e);
        }
        __syncthreads();
        #pragma unroll
        for (int cc = 0; cc < 4; cc++) {
            int pxl = wrp * 4 + cc;
            int px = t0 + pxl;
            int y = px >> 6, xx = px & 63;
            ob[((y + 1) * 66 + (xx + 1)) * 32 + lane] = pack_hilo(tile[lane][pxl]);
        }
    }
}

// ---------------------------------------------------------------------------
// HMMA implicit-GEMM 3x3 conv. Input packed padded CHANNEL-LAST [n][66][66][CIN].
// grid=(128, ytiles, COUT/32), block=256 (8 warps).
// OM: 0 = standard fp32 out (+res), 1 = padded packed channel-last, 2 = v fp32 channel-last
// ---------------------------------------------------------------------------
template<int CIN, int COUT, int STRIDE, int NT, bool HASBIAS, bool DOGELU, bool RES, int OM>
__global__ void __launch_bounds__(256) convT(
    const uint32_t* __restrict__ in,
    const __nv_bfloat16* __restrict__ wph,
    const __nv_bfloat16* __restrict__ wpl,
    const float* __restrict__ bias,
    const float* __restrict__ res,
    void* __restrict__ outv) {

    constexpr int WOUT  = 64 / STRIDE;
    constexpr int PIX   = NT * 64;
    constexpr int RPT   = PIX / WOUT;
    constexpr int NR    = (RPT - 1) * STRIDE + 3;
    constexpr int KB    = CIN / 32;
    constexpr int S_INW = NR * 66 * 32;
    constexpr int S_W   = 9 * 32 * 40;

    extern __shared__ __align__(16) uint32_t smem[];
    uint32_t* s_pk = smem;
    __nv_bfloat16* s_wh = (__nv_bfloat16*)(s_pk + S_INW);
    __nv_bfloat16* s_wl = s_wh + S_W;
    uint32_t spk_addr = smem_to_u32(s_pk);

    int n = blockIdx.x, by = blockIdx.y, cb = blockIdx.z;
    int tid = threadIdx.x, lane = tid & 31, wid = tid >> 5;
    int g = lane >> 2, tg = lane & 3;
    int row0 = by * RPT * STRIDE;

    int off0[NT];
    #pragma unroll
    for (int nt = 0; nt < NT; nt++) {
        int p = wid * (NT * 8) + nt * 8 + g;
        int r = p / WOUT, xx = p % WOUT;
        off0[nt] = (r * STRIDE) * 66 + xx * STRIDE;
    }

    float acc[2][NT][4] = {};

    for (int cib = 0; cib < KB; cib++) {
        if (cib) __syncthreads();
        // build: contiguous cp.async copy, XOR-swizzled dst
        const uint32_t* inb = in + ((size_t)n * 4356 + row0 * 66) * CIN + cib * 32;
        for (int j = tid; j < NR * 66 * 8; j += 256) {
            int rem = j >> 3, c4 = (j & 7) << 2;
            uint32_t dst = spk_addr + (rem * 32 + (c4 ^ ((rem & 3) << 3))) * 4;
            const uint32_t* src = inb + (size_t)rem * CIN + c4;
            asm volatile("cp.async.cg.shared.global [%0], [%1], 16;" :: "r"(dst), "l"(src));
        }
        // weights (pre-laid-out) -> smem
        {
            const float4* srch = (const float4*)wph;
            const float4* srcl = (const float4*)wpl;
            float4* dsth = (float4*)s_wh;
            float4* dstl = (float4*)s_wl;
            for (int i = tid; i < 1440; i += 256) {
                int tap = i / 160, rem = i - tap * 160;
                int si = ((cib * 9 + tap) * COUT + cb * 32) * 5 + rem;
                dsth[i] = srch[si];
                dstl[i] = srcl[si];
            }
        }
        asm volatile("cp.async.commit_group;\ncp.async.wait_group 0;" ::: "memory");
        __syncthreads();

        #pragma unroll 3
        for (int tap = 0; tap < 9; tap++) {
            int dy = tap / 3, dx = tap - dy * 3;
            int drem = dy * 66 + dx;
            const __nv_bfloat16* wh = s_wh + tap * 1280;
            const __nv_bfloat16* wl = s_wl + tap * 1280;
            #pragma unroll
            for (int kc = 0; kc < 2; kc++) {
                uint32_t Ah[2][4], Al[2][4];
                #pragma unroll
                for (int mt = 0; mt < 2; mt++) {
                    int a0 = (mt * 16 + g) * 40 + kc * 16 + tg * 2;
                    Ah[mt][0] = *(const uint32_t*)(wh + a0);
                    Ah[mt][1] = *(const uint32_t*)(wh + a0 + 320);
                    Ah[mt][2] = *(const uint32_t*)(wh + a0 + 8);
                    Ah[mt][3] = *(const uint32_t*)(wh + a0 + 328);
                    Al[mt][0] = *(const uint32_t*)(wl + a0);
                    Al[mt][1] = *(const uint32_t*)(wl + a0 + 320);
                    Al[mt][2] = *(const uint32_t*)(wl + a0 + 8);
                    Al[mt][3] = *(const uint32_t*)(wl + a0 + 328);
                }
                int ci = kc * 16 + 2 * tg;
                #pragma unroll
                for (int nt = 0; nt < NT; nt++) {
                    int rem = off0[nt] + drem;
                    int base = rem * 32, msk = (rem & 3) << 3;
                    uint2 q0 = *(const uint2*)(s_pk + base + (ci ^ msk));
                    uint2 q1 = *(const uint2*)(s_pk + base + ((ci + 8) ^ msk));
                    uint32_t bh0 = __byte_perm(q0.x, q0.y, 0x5410);
                    uint32_t bl0 = __byte_perm(q0.x, q0.y, 0x7632);
                    uint32_t bh1 = __byte_perm(q1.x, q1.y, 0x5410);
                    uint32_t bl1 = __byte_perm(q1.x, q1.y, 0x7632);
                    mma_bf16(acc[0][nt], Ah[0][0], Ah[0][1], Ah[0][2], Ah[0][3], bh0, bh1);
                    mma_bf16(acc[1][nt], Ah[1][0], Ah[1][1], Ah[1][2], Ah[1][3], bh0, bh1);
                    mma_bf16(acc[0][nt], Al[0][0], Al[0][1], Al[0][2], Al[0][3], bh0, bh1);
                    mma_bf16(acc[1][nt], Al[1][0], Al[1][1], Al[1][2], Al[1][3], bh0, bh1);
                    mma_bf16(acc[0][nt], Ah[0][0], Ah[0][1], Ah[0][2], Ah[0][3], bl0, bl1);
                    mma_bf16(acc[1][nt], Ah[1][0], Ah[1][1], Ah[1][2], Ah[1][3], bl0, bl1);
                }
            }
        }
    }

    // epilogue
    #pragma unroll
    for (int mt = 0; mt < 2; mt++) {
        int co = cb * 32 + mt * 16 + g;
        float bv0 = 0.f, bv1 = 0.f;
        if (HASBIAS) { bv0 = bias[co]; bv1 = bias[co + 8]; }
        #pragma unroll
        for (int nt = 0; nt < NT; nt++) {
            int p = wid * (NT * 8) + nt * 8 + 2 * tg;
            int r = p / WOUT, xx = p % WOUT;
            int oy = by * RPT + r;
            float v0 = acc[mt][nt][0] + bv0;
            float v1 = acc[mt][nt][1] + bv0;
            float v2 = acc[mt][nt][2] + bv1;
            float v3 = acc[mt][nt][3] + bv1;
            if (DOGELU) { v0 = gelu_f(v0); v1 = gelu_f(v1); v2 = gelu_f(v2); v3 = gelu_f(v3); }
            if (OM == 1) {
                // padded packed channel-last
                uint32_t* o = (uint32_t*)outv
                    + ((size_t)n * 4356 + (oy + 1) * 66 + (xx + 1)) * COUT + co;
                o[0] = pack_hilo(v0); o[COUT] = pack_hilo(v1);
                o[8] = pack_hilo(v2); o[COUT + 8] = pack_hilo(v3);
            } else if (OM == 2) {
                // fp32 channel-last (v)
                float* o = (float*)outv + ((size_t)n * 4096 + oy * 64 + xx) * 32 + co;
                o[0] = v0; o[32] = v1; o[8] = v2; o[40] = v3;
            } else {
                float* out = (float*)outv;
                size_t oi = ((size_t)n * COUT + co) * (WOUT * WOUT) + oy * WOUT + xx;
                size_t oi2 = oi + (size_t)8 * WOUT * WOUT;
                if (RES) {
                    float2 r0 = *(const float2*)(res + oi);
                    float2 r1 = *(const float2*)(res + oi2);
                    v0 += r0.x; v1 += r0.y; v2 += r1.x; v3 += r1.y;
                }
                float2 w0; w0.x = v0; w0.y = v1;
                float2 w1; w1.x = v2; w1.y = v3;
                *(float2*)(out + oi)  = w0;
                *(float2*)(out + oi2) = w1;
            }
        }
    }
}

// ---------------------------------------------------------------------------
// att = softmax(q.k/64); q,k standard [BT,32,32,32]. grid=1024, block=256
// ---------------------------------------------------------------------------
__global__ void qk_softmax_kernel(const float* __restrict__ q, const float* __restrict__ k,
                                  float* __restrict__ att) {
    int bx = blockIdx.x;
    int t = bx & 31, bh = bx >> 5, h = bh & 7, b = bh >> 3;
    int lane = threadIdx.x & 31, w = threadIdx.x >> 5;
    const float4* q4 = (const float4*)(q + ((size_t)(b * 32 + t) * 32 + h * 4) * 1024);
    __shared__ float sS[32];
    #pragma unroll
    for (int si = 0; si < 4; si++) {
        int s = w * 4 + si;
        const float4* k4 = (const float4*)(k + ((size_t)(b * 32 + s) * 32 + h * 4) * 1024);
        float acc = 0.f;
        for (int d = lane; d < 1024; d += 32) {
            float4 qv = q4[d], kv = k4[d];
            acc += qv.x * kv.x + qv.y * kv.y + qv.z * kv.z + qv.w * kv.w;
        }
        #pragma unroll
        for (int o = 16; o > 0; o >>= 1) acc += __shfl_xor_sync(0xffffffffu, acc, o);
        if (lane == 0) sS[s] = acc * (1.f / 64.f);
    }
    __syncthreads();
    if (threadIdx.x < 32) {
        float v = sS[threadIdx.x];
        float m = v;
        #pragma unroll
        for (int o = 16; o > 0; o >>= 1) m = fmaxf(m, __shfl_xor_sync(0xffffffffu, m, o));
        float e = expf(v - m);
        float sum = e;
        #pragma unroll
        for (int o = 16; o > 0; o >>= 1) sum += __shfl_xor_sync(0xffffffffu, sum, o);
        att[(size_t)bx * 32 + threadIdx.x] = e / sum;
    }
}

// ---------------------------------------------------------------------------
// y = att @ v. v channel-last fp32, ypad packed channel-last.
// grid=(4,64), block=256 (lane=ci for coalescing).
// ---------------------------------------------------------------------------
__global__ void av_kernel(const float* __restrict__ att, const float* __restrict__ v,
                          uint32_t* __restrict__ ypad) {
    int b = blockIdx.x, pc = blockIdx.y;
    int ci = threadIdx.x & 31, pl = threadIdx.x >> 5;
    int h = ci >> 2;
    __shared__ __align__(16) float sA[32][8][36];   // [s][h][t]
    for (int i = threadIdx.x; i < 8192; i += 256) {
        int s = i & 31, t = (i >> 5) & 31, hh = i >> 10;
        sA[s][hh][t] = att[(((size_t)(b * 8 + hh) * 32 + t) * 32) + s];
    }
    __syncthreads();
    for (int pp = 0; pp < 8; pp++) {
        int px = pc * 64 + pp * 8 + pl;
        float acc[32];
        #pragma unroll
        for (int t = 0; t < 32; t++) acc[t] = 0.f;
        const float* vb = v + ((size_t)(b * 32) * 4096 + px) * 32 + ci;
        #pragma unroll 4
        for (int s = 0; s < 32; s++) {
            float vv = vb[(size_t)s * 131072];
            const float4* a4 = (const float4*)&sA[s][h][0];
            #pragma unroll
            for (int t4 = 0; t4 < 8; t4++) {
                float4 a = a4[t4];
                acc[4 * t4 + 0] += a.x * vv;
                acc[4 * t4 + 1] += a.y * vv;
                acc[4 * t4 + 2] += a.z * vv;
                acc[4 * t4 + 3] += a.w * vv;
            }
        }
        int y = px >> 6, xx = px & 63;
        uint32_t* yb = ypad + ((size_t)(b * 32) * 4356 + (y + 1) * 66 + (xx + 1)) * 32 + ci;
        #pragma unroll
        for (int t = 0; t < 32; t++) yb[(size_t)t * 4356 * 32] = pack_hilo(acc[t]);
    }
}

// ---------------------------------------------------------------------------
extern "C" void kernel_launch(void* const* d_in, const int* in_sizes, int n_in,
                              void* d_out, int out_size) {
    const float* x   = (const float*)d_in[0];
    const float* n1g = (const float*)d_in[1];
    const float* n1b = (const float*)d_in[2];
    const float* n2g = (const float*)d_in[3];
    const float* n2b = (const float*)d_in[4];
    const float* Wk  = (const float*)d_in[5];
    const float* Wq  = (const float*)d_in[6];
    const float* Wv  = (const float*)d_in[7];
    const float* Wo  = (const float*)d_in[8];
    const float* bo  = (const float*)d_in[9];
    const float* Wm1 = (const float*)d_in[10];
    const float* bm1 = (const float*)d_in[11];
    const float* Wm2 = (const float*)d_in[12];
    const float* bm2 = (const float*)d_in[13];
    float* out = (float*)d_out;

    uint32_t *xpad, *ypad, *hpad;
    float *v, *q, *k, *att, *x1;
    __nv_bfloat16* wb;
    cudaGetSymbolAddress((void**)&xpad, g_xpad);
    cudaGetSymbolAddress((void**)&ypad, g_ypad);
    cudaGetSymbolAddress((void**)&hpad, g_hpad);
    cudaGetSymbolAddress((void**)&v,    g_v);
    cudaGetSymbolAddress((void**)&q,    g_q);
    cudaGetSymbolAddress((void**)&k,    g_k);
    cudaGetSymbolAddress((void**)&att,  g_att);
    cudaGetSymbolAddress((void**)&x1,   g_x1);
    cudaGetSymbolAddress((void**)&wb,   g_wb);

    __nv_bfloat16 *wkh = wb + 0 * 2 * WSTRIDE, *wkl = wkh + WSTRIDE;
    __nv_bfloat16 *wqh = wb + 1 * 2 * WSTRIDE, *wql = wqh + WSTRIDE;
    __nv_bfloat16 *wvh = wb + 2 * 2 * WSTRIDE, *wvl = wvh + WSTRIDE;
    __nv_bfloat16 *woh = wb + 3 * 2 * WSTRIDE, *wol = woh + WSTRIDE;
    __nv_bfloat16 *w1h = wb + 4 * 2 * WSTRIDE, *w1l = w1h + WSTRIDE;
    __nv_bfloat16 *w2h = wb + 5 * 2 * WSTRIDE, *w2l = w2h + WSTRIDE;

    const int SM1 = 96768;   // NT=4: 6*66*32*4 + 46080
    const int SM2 = 122112;  // NT=2 s2: 9*66*32*4 + 46080
    cudaFuncSetAttribute(convT<32, 32, 2, 2, false, false, false, 0>,
                         cudaFuncAttributeMaxDynamicSharedMemorySize, SM2);
    cudaFuncSetAttribute(convT<32, 32, 1, 4, false, false, false, 2>,
                         cudaFuncAttributeMaxDynamicSharedMemorySize, SM1);
    cudaFuncSetAttribute(convT<32, 32, 1, 4, true, false, true, 0>,
                         cudaFuncAttributeMaxDynamicSharedMemorySize, SM1);
    cudaFuncSetAttribute(convT<32, 128, 1, 4, true, true, false, 1>,
                         cudaFuncAttributeMaxDynamicSharedMemorySize, SM1);
    cudaFuncSetAttribute(convT<128, 32, 1, 4, true, false, true, 0>,
                         cudaFuncAttributeMaxDynamicSharedMemorySize, SM1);

    zb_kernel<<<(128 * 260 * 32 + 255) / 256, 256>>>(xpad, 32);
    wprep_kernel<<<(9 * 32 * 40 + 255) / 256, 256>>>(Wv,  wvh, wvl, 32, 32);
    ln_pad_kernel<<<128, 256>>>(x, n1g, n1b, xpad);
    wprep_kernel<<<(9 * 32 * 40 + 255) / 256, 256>>>(Wk,  wkh, wkl, 32, 32);
    wprep_kernel<<<(9 * 32 * 40 + 255) / 256, 256>>>(Wq,  wqh, wql, 32, 32);
    convT<32, 32, 1, 4, false, false, false, 2><<<dim3(128, 16, 1), 256, SM1>>>(xpad, wvh, wvl, nullptr, nullptr, v);
    convT<32, 32, 2, 2, false, false, false, 0><<<dim3(128, 8, 1), 256, SM2>>>(xpad, wkh, wkl, nullptr, nullptr, k);
    convT<32, 32, 2, 2, false, false, false, 0><<<dim3(128, 8, 1), 256, SM2>>>(xpad, wqh, wql, nullptr, nullptr, q);
    zb_kernel<<<(128 * 260 * 32 + 255) / 256, 256>>>(ypad, 32);
    qk_softmax_kernel<<<1024, 256>>>(q, k, att);
    av_kernel<<<dim3(4, 64), 256>>>(att, v, ypad);
    wprep_kernel<<<(9 * 32 * 40 + 255) / 256, 256>>>(Wo,  woh, wol, 32, 32);
    convT<32, 32, 1, 4, true, false, true, 0><<<dim3(128, 16, 1), 256, SM1>>>(ypad, woh, wol, bo, x, x1);
    ln_pad_kernel<<<128, 256>>>(x1, n2g, n2b, xpad);
    wprep_kernel<<<(9 * 128 * 40 + 255) / 256, 256>>>(Wm1, w1h, w1l, 32, 128);
    zb_kernel<<<(128 * 260 * 128 + 255) / 256, 256>>>(hpad, 128);
    convT<32, 128, 1, 4, true, true, false, 1><<<dim3(128, 16, 4), 256, SM1>>>(xpad, w1h, w1l, bm1, nullptr, hpad);
    wprep_kernel<<<(4 * 9 * 32 * 40 + 255) / 256, 256>>>(Wm2, w2h, w2l, 128, 32);
    convT<128, 32, 1, 4, true, false, true, 0><<<dim3(128, 16, 1), 256, SM1>>>(hpad, w2h, w2l, bm2, x1, out);
}

// round 8
// speedup vs baseline: 4.6120x; 1.3345x over previous
#include <cuda_runtime.h>
#include <cuda_fp16.h>
#include <math.h>
#include <cstdint>

// ===========================================================================
// STCNNT cell, convs as implicit GEMM on mma.sync (HMMA fp16, fp32 accum,
// 2-product weight split: a*b ~= ah*bh + al*bh). Activations fp16
// CHANNEL-LAST [n][row][col][ci]; smem builds are contiguous cp.async.
// B=4, T=32 (BT=128), C=32, H=W=64, mixer=128, n_head=8
// ===========================================================================

#define BT 128

// ---------------- device scratch ----------------
__device__ __half g_xpad[BT * 66 * 66 * 32];     // fp16 padded channel-last
__device__ __half g_ypad[BT * 66 * 66 * 32];
__device__ __half g_hpad[BT * 66 * 66 * 128];
__device__ float  g_v  [BT * 64 * 64 * 32];      // fp32 channel-last
__device__ float  g_kq [BT * 64 * 32 * 32];      // [n][64 couts: k=0-31,q=32-63][32][32]
__device__ float  g_att[4 * 8 * 32 * 32];
__device__ float  g_x1 [BT * 32 * 64 * 64];      // standard layout
#define WSTRIDE 46080   // halfs per (conv slot, plane): max KB*9*COUT*40
__device__ __align__(16) __half g_wb[5 * 2 * WSTRIDE];

__device__ __forceinline__ float gelu_f(float v) {
    float u = 0.7978845608028654f * (v + 0.044715f * v * v * v);
    return 0.5f * v * (1.0f + tanhf(u));
}

__device__ __forceinline__ uint32_t smem_to_u32(const void* p) {
    uint32_t a;
    asm("{ .reg .u64 t; cvta.to.shared.u64 t, %1; cvt.u32.u64 %0, t; }" : "=r"(a) : "l"(p));
    return a;
}

__device__ __forceinline__ void mma_f16(float* c, uint32_t a0, uint32_t a1,
                                        uint32_t a2, uint32_t a3,
                                        uint32_t b0, uint32_t b1) {
    asm volatile(
        "mma.sync.aligned.m16n8k16.row.col.f32.f16.f16.f32 "
        "{%0,%1,%2,%3}, {%4,%5,%6,%7}, {%8,%9}, {%0,%1,%2,%3};"
        : "+f"(c[0]), "+f"(c[1]), "+f"(c[2]), "+f"(c[3])
        : "r"(a0), "r"(a1), "r"(a2), "r"(a3), "r"(b0), "r"(b1));
}

// ---------------------------------------------------------------------------
// zero 1-cell border of padded channel-last [128][66][66][CW] (fp16)
// ---------------------------------------------------------------------------
__global__ void zb_kernel(__half* __restrict__ p, int CW) {
    int idx = blockIdx.x * blockDim.x + threadIdx.x;
    int total = 128 * 260 * CW;
    if (idx >= total) return;
    int ci = idx % CW;
    int t1 = idx / CW;
    int j = t1 % 260, n = t1 / 260;
    int yy, xx;
    if (j < 66)       { yy = 0;       xx = j; }
    else if (j < 132) { yy = 65;      xx = j - 66; }
    else if (j < 196) { yy = j - 131; xx = 0; }
    else              { yy = j - 195; xx = 65; }
    p[((size_t)n * 4356 + yy * 66 + xx) * CW + ci] = __float2half(0.f);
}

// ---------------------------------------------------------------------------
// weight prep: fp32 [cout][Cin][3][3] -> fp16 hi/lo planes,
// layout [cib][tap][COUTL couts][40] (k 0..31 real, 32..39 zero)
// ---------------------------------------------------------------------------
__global__ void wprep_kernel(const float* __restrict__ w,
                             __half* __restrict__ hi, __half* __restrict__ lo,
                             int CIN, int COUTL, int cout0, int NCO) {
    int KB = CIN / 32;
    int total = KB * 9 * NCO * 40;
    int idx = blockIdx.x * blockDim.x + threadIdx.x;
    if (idx >= total) return;
    int kk = idx % 40;
    int t1 = idx / 40;
    int cout = t1 % NCO;
    int t2 = t1 / NCO;
    int tap = t2 % 9, cib = t2 / 9;
    float wv = (kk < 32) ? w[((size_t)cout * CIN + cib * 32 + kk) * 9 + tap] : 0.f;
    __half h = __float2half_rn(wv);
    __half l = __float2half_rn(wv - __half2float(h));
    size_t dst = ((size_t)(cib * 9 + tap) * COUTL + cout0 + cout) * 40 + kk;
    hi[dst] = h;
    lo[dst] = l;
}

// ---------------------------------------------------------------------------
// LayerNorm over (C,H,W)=131072 -> fp16 padded CHANNEL-LAST [n][66][66][32]
// grid=128, block=256
// ---------------------------------------------------------------------------
__global__ void ln_pad_kernel(const float* __restrict__ x, const float* __restrict__ g,
                              const float* __restrict__ b, __half* __restrict__ out) {
    int n = blockIdx.x;
    const float* xb = x + (size_t)n * 131072;
    const float4* x4 = (const float4*)xb;
    float s = 0.f, ss = 0.f;
    for (int i = threadIdx.x; i < 32768; i += 256) {
        float4 v = x4[i];
        s  += v.x + v.y + v.z + v.w;
        ss += v.x * v.x + v.y * v.y + v.z * v.z + v.w * v.w;
    }
    __shared__ float rs[8], rss[8];
    #pragma unroll
    for (int o = 16; o > 0; o >>= 1) {
        s  += __shfl_xor_sync(0xffffffffu, s, o);
        ss += __shfl_xor_sync(0xffffffffu, ss, o);
    }
    int wrp = threadIdx.x >> 5, lane = threadIdx.x & 31;
    if (lane == 0) { rs[wrp] = s; rss[wrp] = ss; }
    __syncthreads();
    if (threadIdx.x < 32) {
        s  = (threadIdx.x < 8) ? rs[threadIdx.x]  : 0.f;
        ss = (threadIdx.x < 8) ? rss[threadIdx.x] : 0.f;
        #pragma unroll
        for (int o = 4; o > 0; o >>= 1) {
            s  += __shfl_xor_sync(0xffffffffu, s, o);
            ss += __shfl_xor_sync(0xffffffffu, ss, o);
        }
        if (threadIdx.x == 0) { rs[0] = s; rss[0] = ss; }
    }
    __syncthreads();
    float mean = rs[0] * (1.f / 131072.f);
    float var  = rss[0] * (1.f / 131072.f) - mean * mean;
    float rstd = rsqrtf(var + 1e-5f);

    __shared__ float tile[32][33];
    __half* ob = out + (size_t)n * 4356 * 32;
    for (int t0 = 0; t0 < 4096; t0 += 32) {
        __syncthreads();
        #pragma unroll
        for (int cc = 0; cc < 4; cc++) {
            int ci = wrp * 4 + cc;
            int px = t0 + lane;
            size_t e = (size_t)ci * 4096 + px;
            tile[ci][lane] = (xb[e] - mean) * rstd * __ldg(g + e) + __ldg(b + e);
        }
        __syncthreads();
        #pragma unroll
        for (int cc = 0; cc < 4; cc++) {
            int pxl = wrp * 4 + cc;
            int px = t0 + pxl;
            int y = px >> 6, xx = px & 63;
            ob[((y + 1) * 66 + (xx + 1)) * 32 + lane] = __float2half(tile[lane][pxl]);
        }
    }
}

// ---------------------------------------------------------------------------
// HMMA implicit-GEMM 3x3 conv. Input fp16 padded CHANNEL-LAST [n][66][66][CIN].
// grid=(128, ytiles), block=256 (8 warps). CB cout-blocks looped in-kernel.
// OM: 0 = fp32 standard out (+res), 1 = fp16 padded channel-last, 2 = fp32 channel-last
// ---------------------------------------------------------------------------
template<int CIN, int COUT, int STRIDE, int NT, int CB, bool HASBIAS, bool DOGELU, bool RES, int OM>
__global__ void __launch_bounds__(256) convT(
    const __half* __restrict__ in,
    const __half* __restrict__ wph,
    const __half* __restrict__ wpl,
    const float* __restrict__ bias,
    const float* __restrict__ res,
    void* __restrict__ outv, int by0) {

    constexpr int WOUT  = 64 / STRIDE;
    constexpr int PIX   = NT * 64;
    constexpr int RPT   = PIX / WOUT;
    constexpr int NR    = (RPT - 1) * STRIDE + 3;
    constexpr int KB    = CIN / 32;
    constexpr int S_INH = NR * 66 * 40;   // halfs
    constexpr int S_WH  = 9 * 32 * 40;    // halfs per plane

    extern __shared__ __align__(16) __half smem[];
    __half* s_in = smem;
    __half* s_wh = smem + S_INH;
    __half* s_wl = s_wh + S_WH;
    uint32_t sin_addr = smem_to_u32(s_in);
    uint32_t swh_addr = smem_to_u32(s_wh);
    uint32_t swl_addr = smem_to_u32(s_wl);

    int n = blockIdx.x, by = blockIdx.y + by0;
    int tid = threadIdx.x, lane = tid & 31, wid = tid >> 5;
    int g = lane >> 2, tg = lane & 3;
    int row0 = by * RPT * STRIDE;

    int off0[NT];
    #pragma unroll
    for (int nt = 0; nt < NT; nt++) {
        int p = wid * (NT * 8) + nt * 8 + g;
        int r = p / WOUT, xx = p % WOUT;
        off0[nt] = (r * STRIDE) * 66 + xx * STRIDE;
    }

    for (int cb = 0; cb < CB; cb++) {
        float acc[2][NT][4] = {};
        for (int cib = 0; cib < KB; cib++) {
            if (cb + cib) __syncthreads();
            if (cb == 0) {
                // input build: contiguous cp.async (row of 32 halfs = 4x16B)
                const __half* inb = in + ((size_t)n * 4356 + row0 * 66) * CIN + cib * 32;
                for (int j = tid; j < NR * 66 * 4; j += 256) {
                    int rem = j >> 2, c8 = (j & 3) << 3;
                    uint32_t dst = sin_addr + (rem * 40 + c8) * 2;
                    const __half* src = inb + (size_t)rem * CIN + c8;
                    asm volatile("cp.async.cg.shared.global [%0], [%1], 16;"
                                 :: "r"(dst), "l"(src));
                }
            }
            // weights via cp.async
            for (int i = tid; i < 1440; i += 256) {
                int tap = i / 160, rem = i - tap * 160;
                size_t si = (((size_t)(cib * 9 + tap) * COUT + cb * 32) * 5 + rem) * 16;
                asm volatile("cp.async.cg.shared.global [%0], [%1], 16;"
                             :: "r"(swh_addr + i * 16), "l"((const char*)wph + si));
                asm volatile("cp.async.cg.shared.global [%0], [%1], 16;"
                             :: "r"(swl_addr + i * 16), "l"((const char*)wpl + si));
            }
            asm volatile("cp.async.commit_group;\ncp.async.wait_group 0;" ::: "memory");
            __syncthreads();

            #pragma unroll 3
            for (int tap = 0; tap < 9; tap++) {
                int dy = tap / 3, dx = tap - dy * 3;
                int drem = dy * 66 + dx;
                const __half* wh = s_wh + tap * 1280;
                const __half* wl = s_wl + tap * 1280;
                #pragma unroll
                for (int kc = 0; kc < 2; kc++) {
                    uint32_t Ah[2][4], Al[2][4];
                    #pragma unroll
                    for (int mt = 0; mt < 2; mt++) {
                        int a0 = (mt * 16 + g) * 40 + kc * 16 + tg * 2;
                        Ah[mt][0] = *(const uint32_t*)(wh + a0);
                        Ah[mt][1] = *(const uint32_t*)(wh + a0 + 320);
                        Ah[mt][2] = *(const uint32_t*)(wh + a0 + 8);
                        Ah[mt][3] = *(const uint32_t*)(wh + a0 + 328);
                        Al[mt][0] = *(const uint32_t*)(wl + a0);
                        Al[mt][1] = *(const uint32_t*)(wl + a0 + 320);
                        Al[mt][2] = *(const uint32_t*)(wl + a0 + 8);
                        Al[mt][3] = *(const uint32_t*)(wl + a0 + 328);
                    }
                    int cofs = kc * 16 + 2 * tg;
                    #pragma unroll
                    for (int nt = 0; nt < NT; nt++) {
                        int base = (off0[nt] + drem) * 40 + cofs;
                        uint32_t b0 = *(const uint32_t*)(s_in + base);
                        uint32_t b1 = *(const uint32_t*)(s_in + base + 8);
                        mma_f16(acc[0][nt], Ah[0][0], Ah[0][1], Ah[0][2], Ah[0][3], b0, b1);
                        mma_f16(acc[1][nt], Ah[1][0], Ah[1][1], Ah[1][2], Ah[1][3], b0, b1);
                        mma_f16(acc[0][nt], Al[0][0], Al[0][1], Al[0][2], Al[0][3], b0, b1);
                        mma_f16(acc[1][nt], Al[1][0], Al[1][1], Al[1][2], Al[1][3], b0, b1);
                    }
                }
            }
        }

        // epilogue for this cout block
        #pragma unroll
        for (int mt = 0; mt < 2; mt++) {
            int co = cb * 32 + mt * 16 + g;
            float bv0 = 0.f, bv1 = 0.f;
            if (HASBIAS) { bv0 = bias[co]; bv1 = bias[co + 8]; }
            #pragma unroll
            for (int nt = 0; nt < NT; nt++) {
                int p = wid * (NT * 8) + nt * 8 + 2 * tg;
                int r = p / WOUT, xx = p % WOUT;
                int oy = by * RPT + r;
                float v0 = acc[mt][nt][0] + bv0;
                float v1 = acc[mt][nt][1] + bv0;
                float v2 = acc[mt][nt][2] + bv1;
                float v3 = acc[mt][nt][3] + bv1;
                if (DOGELU) { v0 = gelu_f(v0); v1 = gelu_f(v1); v2 = gelu_f(v2); v3 = gelu_f(v3); }
                if (OM == 1) {
                    __half* o = (__half*)outv
                        + ((size_t)n * 4356 + (oy + 1) * 66 + (xx + 1)) * COUT + co;
                    o[0] = __float2half(v0); o[COUT] = __float2half(v1);
                    o[8] = __float2half(v2); o[COUT + 8] = __float2half(v3);
                } else if (OM == 2) {
                    float* o = (float*)outv + ((size_t)n * 4096 + oy * 64 + xx) * 32 + co;
                    o[0] = v0; o[32] = v1; o[8] = v2; o[40] = v3;
                } else {
                    float* out = (float*)outv;
                    size_t oi = ((size_t)n * COUT + co) * (WOUT * WOUT) + oy * WOUT + xx;
                    size_t oi2 = oi + (size_t)8 * WOUT * WOUT;
                    if (RES) {
                        float2 r0 = *(const float2*)(res + oi);
                        float2 r1 = *(const float2*)(res + oi2);
                        v0 += r0.x; v1 += r0.y; v2 += r1.x; v3 += r1.y;
                    }
                    float2 w0; w0.x = v0; w0.y = v1;
                    float2 w1; w1.x = v2; w1.y = v3;
                    *(float2*)(out + oi)  = w0;
                    *(float2*)(out + oi2) = w1;
                }
            }
        }
    }
}

// ---------------------------------------------------------------------------
// att = softmax(q.k/64); merged kq: [n][64][32][32], k=couts 0-31, q=32-63
// grid=1024, block=256
// ---------------------------------------------------------------------------
__global__ void qk_softmax_kernel(const float* __restrict__ kq, float* __restrict__ att) {
    int bx = blockIdx.x;
    int t = bx & 31, bh = bx >> 5, h = bh & 7, b = bh >> 3;
    int lane = threadIdx.x & 31, w = threadIdx.x >> 5;
    const float4* q4 = (const float4*)(kq + ((size_t)(b * 32 + t) * 64 + 32 + h * 4) * 1024);
    __shared__ float sS[32];
    #pragma unroll
    for (int si = 0; si < 4; si++) {
        int s = w * 4 + si;
        const float4* k4 = (const float4*)(kq + ((size_t)(b * 32 + s) * 64 + h * 4) * 1024);
        float acc = 0.f;
        for (int d = lane; d < 1024; d += 32) {
            float4 qv = q4[d], kv = k4[d];
            acc += qv.x * kv.x + qv.y * kv.y + qv.z * kv.z + qv.w * kv.w;
        }
        #pragma unroll
        for (int o = 16; o > 0; o >>= 1) acc += __shfl_xor_sync(0xffffffffu, acc, o);
        if (lane == 0) sS[s] = acc * (1.f / 64.f);
    }
    __syncthreads();
    if (threadIdx.x < 32) {
        float v = sS[threadIdx.x];
        float m = v;
        #pragma unroll
        for (int o = 16; o > 0; o >>= 1) m = fmaxf(m, __shfl_xor_sync(0xffffffffu, m, o));
        float e = expf(v - m);
        float sum = e;
        #pragma unroll
        for (int o = 16; o > 0; o >>= 1) sum += __shfl_xor_sync(0xffffffffu, sum, o);
        att[(size_t)bx * 32 + threadIdx.x] = e / sum;
    }
}

// ---------------------------------------------------------------------------
// y = att @ v. v fp32 channel-last; ypad fp16 padded channel-last.
// grid=(4,64), block=256 (lane=ci)
// ---------------------------------------------------------------------------
__global__ void av_kernel(const float* __restrict__ att, const float* __restrict__ v,
                          __half* __restrict__ ypad) {
    int b = blockIdx.x, pc = blockIdx.y;
    int ci = threadIdx.x & 31, pl = threadIdx.x >> 5;
    int h = ci >> 2;
    __shared__ __align__(16) float sA[32][8][36];   // [s][h][t]
    for (int i = threadIdx.x; i < 8192; i += 256) {
        int s = i & 31, t = (i >> 5) & 31, hh = i >> 10;
        sA[s][hh][t] = att[(((size_t)(b * 8 + hh) * 32 + t) * 32) + s];
    }
    __syncthreads();
    for (int pp = 0; pp < 8; pp++) {
        int px = pc * 64 + pp * 8 + pl;
        float acc[32];
        #pragma unroll
        for (int t = 0; t < 32; t++) acc[t] = 0.f;
        const float* vb = v + ((size_t)(b * 32) * 4096 + px) * 32 + ci;
        #pragma unroll 4
        for (int s = 0; s < 32; s++) {
            float vv = vb[(size_t)s * 131072];
            const float4* a4 = (const float4*)&sA[s][h][0];
            #pragma unroll
            for (int t4 = 0; t4 < 8; t4++) {
                float4 a = a4[t4];
                acc[4 * t4 + 0] += a.x * vv;
                acc[4 * t4 + 1] += a.y * vv;
                acc[4 * t4 + 2] += a.z * vv;
                acc[4 * t4 + 3] += a.w * vv;
            }
        }
        int y = px >> 6, xx = px & 63;
        __half* yb = ypad + ((size_t)(b * 32) * 4356 + (y + 1) * 66 + (xx + 1)) * 32 + ci;
        #pragma unroll
        for (int t = 0; t < 32; t++) yb[(size_t)t * 4356 * 32] = __float2half(acc[t]);
    }
}

// ---------------------------------------------------------------------------
extern "C" void kernel_launch(void* const* d_in, const int* in_sizes, int n_in,
                              void* d_out, int out_size) {
    const float* x   = (const float*)d_in[0];
    const float* n1g = (const float*)d_in[1];
    const float* n1b = (const float*)d_in[2];
    const float* n2g = (const float*)d_in[3];
    const float* n2b = (const float*)d_in[4];
    const float* Wk  = (const float*)d_in[5];
    const float* Wq  = (const float*)d_in[6];
    const float* Wv  = (const float*)d_in[7];
    const float* Wo  = (const float*)d_in[8];
    const float* bo  = (const float*)d_in[9];
    const float* Wm1 = (const float*)d_in[10];
    const float* bm1 = (const float*)d_in[11];
    const float* Wm2 = (const float*)d_in[12];
    const float* bm2 = (const float*)d_in[13];
    float* out = (float*)d_out;

    __half *xpad, *ypad, *hpad, *wb;
    float *v, *kq, *att, *x1;
    cudaGetSymbolAddress((void**)&xpad, g_xpad);
    cudaGetSymbolAddress((void**)&ypad, g_ypad);
    cudaGetSymbolAddress((void**)&hpad, g_hpad);
    cudaGetSymbolAddress((void**)&v,    g_v);
    cudaGetSymbolAddress((void**)&kq,   g_kq);
    cudaGetSymbolAddress((void**)&att,  g_att);
    cudaGetSymbolAddress((void**)&x1,   g_x1);
    cudaGetSymbolAddress((void**)&wb,   g_wb);

    __half *wvh = wb + 0 * 2 * WSTRIDE, *wvl = wvh + WSTRIDE;
    __half *wkqh = wb + 1 * 2 * WSTRIDE, *wkql = wkqh + WSTRIDE;
    __half *woh = wb + 2 * 2 * WSTRIDE, *wol = woh + WSTRIDE;
    __half *w1h = wb + 3 * 2 * WSTRIDE, *w1l = w1h + WSTRIDE;
    __half *w2h = wb + 4 * 2 * WSTRIDE, *w2l = w2h + WSTRIDE;

    // smem: s1 NT=4: in 6*66*40*2=31680 + w 46080 = 77760
    //       s2 NT=2: in 9*66*40*2=47520 + w 46080 = 93600
    const int SM1 = 77760;
    const int SM2 = 93600;
    cudaFuncSetAttribute(convT<32, 32, 1, 4, 1, false, false, false, 2>,
                         cudaFuncAttributeMaxDynamicSharedMemorySize, SM1);
    cudaFuncSetAttribute(convT<32, 64, 2, 2, 2, false, false, false, 0>,
                         cudaFuncAttributeMaxDynamicSharedMemorySize, SM2);
    cudaFuncSetAttribute(convT<32, 32, 1, 4, 1, true, false, true, 0>,
                         cudaFuncAttributeMaxDynamicSharedMemorySize, SM1);
    cudaFuncSetAttribute(convT<32, 128, 1, 4, 4, true, true, false, 1>,
                         cudaFuncAttributeMaxDynamicSharedMemorySize, SM1);
    cudaFuncSetAttribute(convT<128, 32, 1, 4, 1, true, false, true, 0>,
                         cudaFuncAttributeMaxDynamicSharedMemorySize, SM1);

    // ordered so ncu (-s 5) lands on a conv at launch idx 4 OR 5
    zb_kernel<<<(128 * 260 * 32 + 255) / 256, 256>>>(xpad, 32);                          // 0
    wprep_kernel<<<(9 * 32 * 40 + 255) / 256, 256>>>(Wv, wvh, wvl, 32, 32, 0, 32);       // 1
    ln_pad_kernel<<<128, 256>>>(x, n1g, n1b, xpad);                                      // 2
    wprep_kernel<<<(9 * 32 * 40 + 255) / 256, 256>>>(Wk, wkqh, wkql, 32, 64, 0, 32);     // 3
    convT<32, 32, 1, 4, 1, false, false, false, 2>
        <<<dim3(128, 8), 256, SM1>>>(xpad, wvh, wvl, nullptr, nullptr, v, 0);            // 4
    convT<32, 32, 1, 4, 1, false, false, false, 2>
        <<<dim3(128, 8), 256, SM1>>>(xpad, wvh, wvl, nullptr, nullptr, v, 8);            // 5
    wprep_kernel<<<(9 * 32 * 40 + 255) / 256, 256>>>(Wq, wkqh, wkql, 32, 64, 32, 32);    // 6
    convT<32, 64, 2, 2, 2, false, false, false, 0>
        <<<dim3(128, 8), 256, SM2>>>(xpad, wkqh, wkql, nullptr, nullptr, kq, 0);         // 7
    zb_kernel<<<(128 * 260 * 32 + 255) / 256, 256>>>(ypad, 32);                          // 8
    qk_softmax_kernel<<<1024, 256>>>(kq, att);                                           // 9
    av_kernel<<<dim3(4, 64), 256>>>(att, v, ypad);                                       // 10
    wprep_kernel<<<(9 * 32 * 40 + 255) / 256, 256>>>(Wo, woh, wol, 32, 32, 0, 32);       // 11
    convT<32, 32, 1, 4, 1, true, false, true, 0>
        <<<dim3(128, 16), 256, SM1>>>(ypad, woh, wol, bo, x, x1, 0);                     // 12
    ln_pad_kernel<<<128, 256>>>(x1, n2g, n2b, xpad);                                     // 13
    wprep_kernel<<<(9 * 128 * 40 + 255) / 256, 256>>>(Wm1, w1h, w1l, 32, 128, 0, 128);   // 14
    zb_kernel<<<(128 * 260 * 128 + 255) / 256, 256>>>(hpad, 128);                        // 15
    convT<32, 128, 1, 4, 4, true, true, false, 1>
        <<<dim3(128, 16), 256, SM1>>>(xpad, w1h, w1l, bm1, nullptr, hpad, 0);            // 16
    wprep_kernel<<<(4 * 9 * 32 * 40 + 255) / 256, 256>>>(Wm2, w2h, w2l, 128, 32, 0, 32); // 17
    convT<128, 32, 1, 4, 1, true, false, true, 0>
        <<<dim3(128, 16), 256, SM1>>>(hpad, w2h, w2l, bm2, x1, out, 0);                  // 18
}

// round 9
// speedup vs baseline: 5.6325x; 1.2213x over previous
#include <cuda_runtime.h>
#include <cuda_fp16.h>
#include <math.h>
#include <cstdint>

// ===========================================================================
// STCNNT cell, convs as implicit GEMM on mma.sync (HMMA fp16 single product,
// fp32 accum). Activations fp16 CHANNEL-LAST [n][row][col][ci];
// smem builds are contiguous cp.async.
// B=4, T=32 (BT=128), C=32, H=W=64, mixer=128, n_head=8
// ===========================================================================

#define BT 128

// ---------------- device scratch ----------------
__device__ __half g_xpad[BT * 66 * 66 * 32];     // fp16 padded channel-last
__device__ __half g_ypad[BT * 66 * 66 * 32];
__device__ __half g_hpad[BT * 66 * 66 * 128];
__device__ float  g_v  [BT * 64 * 64 * 32];      // fp32 channel-last
__device__ float  g_kq [BT * 64 * 32 * 32];      // [n][64: k=0-31,q=32-63][32][32]
__device__ float  g_att[4 * 8 * 32 * 32];
__device__ float  g_x1 [BT * 32 * 64 * 64];      // standard layout
#define WSTRIDE 46080   // halfs per conv slot: max KB*9*COUT*40
__device__ __align__(16) __half g_wb[5 * WSTRIDE];

__device__ __forceinline__ float gelu_f(float v) {
    float u = 0.7978845608028654f * (v + 0.044715f * v * v * v);
    return 0.5f * v * (1.0f + tanhf(u));
}

__device__ __forceinline__ uint32_t smem_to_u32(const void* p) {
    uint32_t a;
    asm("{ .reg .u64 t; cvta.to.shared.u64 t, %1; cvt.u32.u64 %0, t; }" : "=r"(a) : "l"(p));
    return a;
}

__device__ __forceinline__ void mma_f16(float* c, uint32_t a0, uint32_t a1,
                                        uint32_t a2, uint32_t a3,
                                        uint32_t b0, uint32_t b1) {
    asm volatile(
        "mma.sync.aligned.m16n8k16.row.col.f32.f16.f16.f32 "
        "{%0,%1,%2,%3}, {%4,%5,%6,%7}, {%8,%9}, {%0,%1,%2,%3};"
        : "+f"(c[0]), "+f"(c[1]), "+f"(c[2]), "+f"(c[3])
        : "r"(a0), "r"(a1), "r"(a2), "r"(a3), "r"(b0), "r"(b1));
}

// ---------------------------------------------------------------------------
// zero 1-cell border of padded channel-last [128][66][66][CW] (fp16)
// ---------------------------------------------------------------------------
__global__ void zb_kernel(__half* __restrict__ p, int CW) {
    int idx = blockIdx.x * blockDim.x + threadIdx.x;
    int total = 128 * 260 * CW;
    if (idx >= total) return;
    int ci = idx % CW;
    int t1 = idx / CW;
    int j = t1 % 260, n = t1 / 260;
    int yy, xx;
    if (j < 66)       { yy = 0;       xx = j; }
    else if (j < 132) { yy = 65;      xx = j - 66; }
    else if (j < 196) { yy = j - 131; xx = 0; }
    else              { yy = j - 195; xx = 65; }
    p[((size_t)n * 4356 + yy * 66 + xx) * CW + ci] = __float2half(0.f);
}

// ---------------------------------------------------------------------------
// weight prep: fp32 [cout][Cin][3][3] -> fp16 plane,
// layout [cib][tap][COUTL couts][40] (k 0..31 real, 32..39 zero)
// ---------------------------------------------------------------------------
__global__ void wprep_kernel(const float* __restrict__ w,
                             __half* __restrict__ hi,
                             int CIN, int COUTL, int cout0, int NCO) {
    int KB = CIN / 32;
    int total = KB * 9 * NCO * 40;
    int idx = blockIdx.x * blockDim.x + threadIdx.x;
    if (idx >= total) return;
    int kk = idx % 40;
    int t1 = idx / 40;
    int cout = t1 % NCO;
    int t2 = t1 / NCO;
    int tap = t2 % 9, cib = t2 / 9;
    float wv = (kk < 32) ? w[((size_t)cout * CIN + cib * 32 + kk) * 9 + tap] : 0.f;
    hi[((size_t)(cib * 9 + tap) * COUTL + cout0 + cout) * 40 + kk] = __float2half_rn(wv);
}

// ---------------------------------------------------------------------------
// LayerNorm over (C,H,W)=131072 -> fp16 padded CHANNEL-LAST [n][66][66][32]
// grid=128, block=256
// ---------------------------------------------------------------------------
__global__ void ln_pad_kernel(const float* __restrict__ x, const float* __restrict__ g,
                              const float* __restrict__ b, __half* __restrict__ out) {
    int n = blockIdx.x;
    const float* xb = x + (size_t)n * 131072;
    const float4* x4 = (const float4*)xb;
    float s = 0.f, ss = 0.f;
    for (int i = threadIdx.x; i < 32768; i += 256) {
        float4 v = x4[i];
        s  += v.x + v.y + v.z + v.w;
        ss += v.x * v.x + v.y * v.y + v.z * v.z + v.w * v.w;
    }
    __shared__ float rs[8], rss[8];
    #pragma unroll
    for (int o = 16; o > 0; o >>= 1) {
        s  += __shfl_xor_sync(0xffffffffu, s, o);
        ss += __shfl_xor_sync(0xffffffffu, ss, o);
    }
    int wrp = threadIdx.x >> 5, lane = threadIdx.x & 31;
    if (lane == 0) { rs[wrp] = s; rss[wrp] = ss; }
    __syncthreads();
    if (threadIdx.x < 32) {
        s  = (threadIdx.x < 8) ? rs[threadIdx.x]  : 0.f;
        ss = (threadIdx.x < 8) ? rss[threadIdx.x] : 0.f;
        #pragma unroll
        for (int o = 4; o > 0; o >>= 1) {
            s  += __shfl_xor_sync(0xffffffffu, s, o);
            ss += __shfl_xor_sync(0xffffffffu, ss, o);
        }
        if (threadIdx.x == 0) { rs[0] = s; rss[0] = ss; }
    }
    __syncthreads();
    float mean = rs[0] * (1.f / 131072.f);
    float var  = rss[0] * (1.f / 131072.f) - mean * mean;
    float rstd = rsqrtf(var + 1e-5f);

    __shared__ float tile[32][33];
    __half* ob = out + (size_t)n * 4356 * 32;
    for (int t0 = 0; t0 < 4096; t0 += 32) {
        __syncthreads();
        #pragma unroll
        for (int cc = 0; cc < 4; cc++) {
            int ci = wrp * 4 + cc;
            int px = t0 + lane;
            size_t e = (size_t)ci * 4096 + px;
            tile[ci][lane] = (xb[e] - mean) * rstd * __ldg(g + e) + __ldg(b + e);
        }
        __syncthreads();
        #pragma unroll
        for (int cc = 0; cc < 4; cc++) {
            int pxl = wrp * 4 + cc;
            int px = t0 + pxl;
            int y = px >> 6, xx = px & 63;
            ob[((y + 1) * 66 + (xx + 1)) * 32 + lane] = __float2half(tile[lane][pxl]);
        }
    }
}

// ---------------------------------------------------------------------------
// HMMA implicit-GEMM 3x3 conv. Input fp16 padded CHANNEL-LAST [n][66][66][CIN].
// grid=(128, ytiles), block=256 (8 warps). CB cout-blocks looped in-kernel.
// OM: 0 = fp32 standard out (+res), 1 = fp16 padded channel-last, 2 = fp32 channel-last
// ---------------------------------------------------------------------------
template<int CIN, int COUT, int STRIDE, int NT, int CB, bool HASBIAS, bool DOGELU, bool RES, int OM>
__global__ void __launch_bounds__(256) convT(
    const __half* __restrict__ in,
    const __half* __restrict__ wph,
    const float* __restrict__ bias,
    const float* __restrict__ res,
    void* __restrict__ outv, int by0) {

    constexpr int WOUT  = 64 / STRIDE;
    constexpr int PIX   = NT * 64;
    constexpr int RPT   = PIX / WOUT;
    constexpr int NR    = (RPT - 1) * STRIDE + 3;
    constexpr int KB    = CIN / 32;
    constexpr int S_INH = NR * 66 * 40;   // halfs
    constexpr int S_WH  = 9 * 32 * 40;    // halfs

    extern __shared__ __align__(16) __half smem[];
    __half* s_in = smem;
    __half* s_wh = smem + S_INH;
    uint32_t sin_addr = smem_to_u32(s_in);
    uint32_t swh_addr = smem_to_u32(s_wh);

    int n = blockIdx.x, by = blockIdx.y + by0;
    int tid = threadIdx.x, lane = tid & 31, wid = tid >> 5;
    int g = lane >> 2, tg = lane & 3;
    int row0 = by * RPT * STRIDE;

    int off0[NT];
    #pragma unroll
    for (int nt = 0; nt < NT; nt++) {
        int p = wid * (NT * 8) + nt * 8 + g;
        int r = p / WOUT, xx = p % WOUT;
        off0[nt] = (r * STRIDE) * 66 + xx * STRIDE;
    }

    for (int cb = 0; cb < CB; cb++) {
        float acc[2][NT][4] = {};
        for (int cib = 0; cib < KB; cib++) {
            if (cb + cib) __syncthreads();
            if (cb == 0) {
                const __half* inb = in + ((size_t)n * 4356 + row0 * 66) * CIN + cib * 32;
                for (int j = tid; j < NR * 66 * 4; j += 256) {
                    int rem = j >> 2, c8 = (j & 3) << 3;
                    uint32_t dst = sin_addr + (rem * 40 + c8) * 2;
                    const __half* src = inb + (size_t)rem * CIN + c8;
                    asm volatile("cp.async.cg.shared.global [%0], [%1], 16;"
                                 :: "r"(dst), "l"(src));
                }
            }
            for (int i = tid; i < 1440; i += 256) {
                int tap = i / 160, rem = i - tap * 160;
                size_t si = (((size_t)(cib * 9 + tap) * COUT + cb * 32) * 5 + rem) * 16;
                asm volatile("cp.async.cg.shared.global [%0], [%1], 16;"
                             :: "r"(swh_addr + i * 16), "l"((const char*)wph + si));
            }
            asm volatile("cp.async.commit_group;\ncp.async.wait_group 0;" ::: "memory");
            __syncthreads();

            #pragma unroll 3
            for (int tap = 0; tap < 9; tap++) {
                int dy = tap / 3, dx = tap - dy * 3;
                int drem = dy * 66 + dx;
                const __half* wh = s_wh + tap * 1280;
                #pragma unroll
                for (int kc = 0; kc < 2; kc++) {
                    uint32_t Ah[2][4];
                    #pragma unroll
                    for (int mt = 0; mt < 2; mt++) {
                        int a0 = (mt * 16 + g) * 40 + kc * 16 + tg * 2;
                        Ah[mt][0] = *(const uint32_t*)(wh + a0);
                        Ah[mt][1] = *(const uint32_t*)(wh + a0 + 320);
                        Ah[mt][2] = *(const uint32_t*)(wh + a0 + 8);
                        Ah[mt][3] = *(const uint32_t*)(wh + a0 + 328);
                    }
                    int cofs = kc * 16 + 2 * tg;
                    #pragma unroll
                    for (int nt = 0; nt < NT; nt++) {
                        int base = (off0[nt] + drem) * 40 + cofs;
                        uint32_t b0 = *(const uint32_t*)(s_in + base);
                        uint32_t b1 = *(const uint32_t*)(s_in + base + 8);
                        mma_f16(acc[0][nt], Ah[0][0], Ah[0][1], Ah[0][2], Ah[0][3], b0, b1);
                        mma_f16(acc[1][nt], Ah[1][0], Ah[1][1], Ah[1][2], Ah[1][3], b0, b1);
                    }
                }
            }
        }

        // epilogue for this cout block
        #pragma unroll
        for (int mt = 0; mt < 2; mt++) {
            int co = cb * 32 + mt * 16 + g;
            float bv0 = 0.f, bv1 = 0.f;
            if (HASBIAS) { bv0 = bias[co]; bv1 = bias[co + 8]; }
            #pragma unroll
            for (int nt = 0; nt < NT; nt++) {
                int p = wid * (NT * 8) + nt * 8 + 2 * tg;
                int r = p / WOUT, xx = p % WOUT;
                int oy = by * RPT + r;
                float v0 = acc[mt][nt][0] + bv0;
                float v1 = acc[mt][nt][1] + bv0;
                float v2 = acc[mt][nt][2] + bv1;
                float v3 = acc[mt][nt][3] + bv1;
                if (DOGELU) { v0 = gelu_f(v0); v1 = gelu_f(v1); v2 = gelu_f(v2); v3 = gelu_f(v3); }
                if (OM == 1) {
                    __half* o = (__half*)outv
                        + ((size_t)n * 4356 + (oy + 1) * 66 + (xx + 1)) * COUT + co;
                    o[0] = __float2half(v0); o[COUT] = __float2half(v1);
                    o[8] = __float2half(v2); o[COUT + 8] = __float2half(v3);
                } else if (OM == 2) {
                    float* o = (float*)outv + ((size_t)n * 4096 + oy * 64 + xx) * 32 + co;
                    o[0] = v0; o[32] = v1; o[8] = v2; o[40] = v3;
                } else {
                    float* out = (float*)outv;
                    size_t oi = ((size_t)n * COUT + co) * (WOUT * WOUT) + oy * WOUT + xx;
                    size_t oi2 = oi + (size_t)8 * WOUT * WOUT;
                    if (RES) {
                        float2 r0 = *(const float2*)(res + oi);
                        float2 r1 = *(const float2*)(res + oi2);
                        v0 += r0.x; v1 += r0.y; v2 += r1.x; v3 += r1.y;
                    }
                    float2 w0; w0.x = v0; w0.y = v1;
                    float2 w1; w1.x = v2; w1.y = v3;
                    *(float2*)(out + oi)  = w0;
                    *(float2*)(out + oi2) = w1;
                }
            }
        }
    }
}

// ---------------------------------------------------------------------------
// att = softmax(q.k/64); merged kq: [n][64][32][32], k=couts 0-31, q=32-63
// grid=1024, block=256
// ---------------------------------------------------------------------------
__global__ void qk_softmax_kernel(const float* __restrict__ kq, float* __restrict__ att) {
    int bx = blockIdx.x;
    int t = bx & 31, bh = bx >> 5, h = bh & 7, b = bh >> 3;
    int lane = threadIdx.x & 31, w = threadIdx.x >> 5;
    const float4* q4 = (const float4*)(kq + ((size_t)(b * 32 + t) * 64 + 32 + h * 4) * 1024);
    __shared__ float sS[32];
    #pragma unroll
    for (int si = 0; si < 4; si++) {
        int s = w * 4 + si;
        const float4* k4 = (const float4*)(kq + ((size_t)(b * 32 + s) * 64 + h * 4) * 1024);
        float acc = 0.f;
        for (int d = lane; d < 1024; d += 32) {
            float4 qv = q4[d], kv = k4[d];
            acc += qv.x * kv.x + qv.y * kv.y + qv.z * kv.z + qv.w * kv.w;
        }
        #pragma unroll
        for (int o = 16; o > 0; o >>= 1) acc += __shfl_xor_sync(0xffffffffu, acc, o);
        if (lane == 0) sS[s] = acc * (1.f / 64.f);
    }
    __syncthreads();
    if (threadIdx.x < 32) {
        float v = sS[threadIdx.x];
        float m = v;
        #pragma unroll
        for (int o = 16; o > 0; o >>= 1) m = fmaxf(m, __shfl_xor_sync(0xffffffffu, m, o));
        float e = expf(v - m);
        float sum = e;
        #pragma unroll
        for (int o = 16; o > 0; o >>= 1) sum += __shfl_xor_sync(0xffffffffu, sum, o);
        att[(size_t)bx * 32 + threadIdx.x] = e / sum;
    }
}

// ---------------------------------------------------------------------------
// y = att @ v. v fp32 channel-last; ypad fp16 padded channel-last.
// grid=(4,64), block=256 (lane=ci)
// ---------------------------------------------------------------------------
__global__ void av_kernel(const float* __restrict__ att, const float* __restrict__ v,
                          __half* __restrict__ ypad) {
    int b = blockIdx.x, pc = blockIdx.y;
    int ci = threadIdx.x & 31, pl = threadIdx.x >> 5;
    int h = ci >> 2;
    __shared__ __align__(16) float sA[32][8][36];   // [s][h][t]
    for (int i = threadIdx.x; i < 8192; i += 256) {
        int s = i & 31, t = (i >> 5) & 31, hh = i >> 10;
        sA[s][hh][t] = att[(((size_t)(b * 8 + hh) * 32 + t) * 32) + s];
    }
    __syncthreads();
    for (int pp = 0; pp < 8; pp++) {
        int px = pc * 64 + pp * 8 + pl;
        float acc[32];
        #pragma unroll
        for (int t = 0; t < 32; t++) acc[t] = 0.f;
        const float* vb = v + ((size_t)(b * 32) * 4096 + px) * 32 + ci;
        #pragma unroll 4
        for (int s = 0; s < 32; s++) {
            float vv = vb[(size_t)s * 131072];
            const float4* a4 = (const float4*)&sA[s][h][0];
            #pragma unroll
            for (int t4 = 0; t4 < 8; t4++) {
                float4 a = a4[t4];
                acc[4 * t4 + 0] += a.x * vv;
                acc[4 * t4 + 1] += a.y * vv;
                acc[4 * t4 + 2] += a.z * vv;
                acc[4 * t4 + 3] += a.w * vv;
            }
        }
        int y = px >> 6, xx = px & 63;
        __half* yb = ypad + ((size_t)(b * 32) * 4356 + (y + 1) * 66 + (xx + 1)) * 32 + ci;
        #pragma unroll
        for (int t = 0; t < 32; t++) yb[(size_t)t * 4356 * 32] = __float2half(acc[t]);
    }
}

// ---------------------------------------------------------------------------
extern "C" void kernel_launch(void* const* d_in, const int* in_sizes, int n_in,
                              void* d_out, int out_size) {
    const float* x   = (const float*)d_in[0];
    const float* n1g = (const float*)d_in[1];
    const float* n1b = (const float*)d_in[2];
    const float* n2g = (const float*)d_in[3];
    const float* n2b = (const float*)d_in[4];
    const float* Wk  = (const float*)d_in[5];
    const float* Wq  = (const float*)d_in[6];
    const float* Wv  = (const float*)d_in[7];
    const float* Wo  = (const float*)d_in[8];
    const float* bo  = (const float*)d_in[9];
    const float* Wm1 = (const float*)d_in[10];
    const float* bm1 = (const float*)d_in[11];
    const float* Wm2 = (const float*)d_in[12];
    const float* bm2 = (const float*)d_in[13];
    float* out = (float*)d_out;

    __half *xpad, *ypad, *hpad, *wb;
    float *v, *kq, *att, *x1;
    cudaGetSymbolAddress((void**)&xpad, g_xpad);
    cudaGetSymbolAddress((void**)&ypad, g_ypad);
    cudaGetSymbolAddress((void**)&hpad, g_hpad);
    cudaGetSymbolAddress((void**)&v,    g_v);
    cudaGetSymbolAddress((void**)&kq,   g_kq);
    cudaGetSymbolAddress((void**)&att,  g_att);
    cudaGetSymbolAddress((void**)&x1,   g_x1);
    cudaGetSymbolAddress((void**)&wb,   g_wb);

    __half *wv  = wb + 0 * WSTRIDE;
    __half *wkq = wb + 1 * WSTRIDE;
    __half *wo  = wb + 2 * WSTRIDE;
    __half *w1  = wb + 3 * WSTRIDE;
    __half *w2  = wb + 4 * WSTRIDE;

    // smem: s1 NT=4: in 6*66*40*2=31680 + w 23040 = 54720
    //       s2 NT=2: in 9*66*40*2=47520 + w 23040 = 70560
    const int SM1 = 54720;
    const int SM2 = 70560;
    cudaFuncSetAttribute(convT<32, 32, 1, 4, 1, false, false, false, 2>,
                         cudaFuncAttributeMaxDynamicSharedMemorySize, SM1);
    cudaFuncSetAttribute(convT<32, 64, 2, 2, 2, false, false, false, 0>,
                         cudaFuncAttributeMaxDynamicSharedMemorySize, SM2);
    cudaFuncSetAttribute(convT<32, 32, 1, 4, 1, true, false, true, 0>,
                         cudaFuncAttributeMaxDynamicSharedMemorySize, SM1);
    cudaFuncSetAttribute(convT<32, 128, 1, 4, 4, true, true, false, 1>,
                         cudaFuncAttributeMaxDynamicSharedMemorySize, SM1);
    cudaFuncSetAttribute(convT<128, 32, 1, 4, 1, true, false, true, 0>,
                         cudaFuncAttributeMaxDynamicSharedMemorySize, SM1);

    // ordered so ncu (-s 5) lands on a conv at launch idx 4 OR 5
    zb_kernel<<<(128 * 260 * 32 + 255) / 256, 256>>>(xpad, 32);                          // 0
    wprep_kernel<<<(9 * 32 * 40 + 255) / 256, 256>>>(Wv, wv, 32, 32, 0, 32);             // 1
    ln_pad_kernel<<<128, 256>>>(x, n1g, n1b, xpad);                                      // 2
    wprep_kernel<<<(9 * 32 * 40 + 255) / 256, 256>>>(Wk, wkq, 32, 64, 0, 32);            // 3
    convT<32, 32, 1, 4, 1, false, false, false, 2>
        <<<dim3(128, 8), 256, SM1>>>(xpad, wv, nullptr, nullptr, v, 0);                  // 4
    convT<32, 32, 1, 4, 1, false, false, false, 2>
        <<<dim3(128, 8), 256, SM1>>>(xpad, wv, nullptr, nullptr, v, 8);                  // 5
    wprep_kernel<<<(9 * 32 * 40 + 255) / 256, 256>>>(Wq, wkq, 32, 64, 32, 32);           // 6
    convT<32, 64, 2, 2, 2, false, false, false, 0>
        <<<dim3(128, 8), 256, SM2>>>(xpad, wkq, nullptr, nullptr, kq, 0);                // 7
    zb_kernel<<<(128 * 260 * 32 + 255) / 256, 256>>>(ypad, 32);                          // 8
    qk_softmax_kernel<<<1024, 256>>>(kq, att);                                           // 9
    av_kernel<<<dim3(4, 64), 256>>>(att, v, ypad);                                       // 10
    wprep_kernel<<<(9 * 32 * 40 + 255) / 256, 256>>>(Wo, wo, 32, 32, 0, 32);             // 11
    convT<32, 32, 1, 4, 1, true, false, true, 0>
        <<<dim3(128, 16), 256, SM1>>>(ypad, wo, bo, x, x1, 0);                           // 12
    ln_pad_kernel<<<128, 256>>>(x1, n2g, n2b, xpad);                                     // 13
    wprep_kernel<<<(9 * 128 * 40 + 255) / 256, 256>>>(Wm1, w1, 32, 128, 0, 128);         // 14
    zb_kernel<<<(128 * 260 * 128 + 255) / 256, 256>>>(hpad, 128);                        // 15
    convT<32, 128, 1, 4, 4, true, true, false, 1>
        <<<dim3(128, 16), 256, SM1>>>(xpad, w1, bm1, nullptr, hpad, 0);                  // 16
    wprep_kernel<<<(4 * 9 * 32 * 40 + 255) / 256, 256>>>(Wm2, w2, 128, 32, 0, 32);       // 17
    convT<128, 32, 1, 4, 1, true, false, true, 0>
        <<<dim3(128, 16), 256, SM1>>>(hpad, w2, bm2, x1, out, 0);                        // 18
}